// round 1
// baseline (speedup 1.0000x reference)
#include <cuda_runtime.h>
#include <math.h>
#include <stddef.h>

// ---------------- problem constants ----------------
#define BATCH   4
#define SEQ     2048
#define DIM     1024
#define HEADS   16
#define DH      64
#define HID     4096
#define TOK     (BATCH * SEQ)          // 8192
#define EPS     1e-5f
#define ATT_SCALE 0.03125f             // DIM^-0.5 = 1/32

// ---------------- scratch (no cudaMalloc allowed) ----------------
__device__ float g_xn [TOK * DIM];        // 32 MB
__device__ float g_qkv[TOK * 3 * DIM];    // 96 MB
__device__ float g_att[TOK * DIM];        // 32 MB
__device__ float g_x1 [TOK * DIM];        // 32 MB
__device__ float g_h  [TOK * DIM];        // 32 MB
__device__ float g_ff [TOK * HID];        // 128 MB

// =====================================================================
// LayerNorm (torch semantics: unbiased std, denominator (std + eps))
// one block per row, 256 threads, 4 elements/thread
// =====================================================================
__global__ void __launch_bounds__(256) ln_kernel(
    const float* __restrict__ x, const float* __restrict__ gamma,
    const float* __restrict__ beta, float* __restrict__ y)
{
    int row = blockIdx.x;
    int t = threadIdx.x;
    const float* xr = x + (size_t)row * DIM;
    float4 v = *(const float4*)(xr + t * 4);

    __shared__ float red[8];

    float s = v.x + v.y + v.z + v.w;
#pragma unroll
    for (int o = 16; o > 0; o >>= 1) s += __shfl_xor_sync(0xffffffffu, s, o);
    if ((t & 31) == 0) red[t >> 5] = s;
    __syncthreads();
    float tot = 0.f;
#pragma unroll
    for (int i = 0; i < 8; i++) tot += red[i];
    float mean = tot * (1.0f / DIM);

    float dx = v.x - mean, dy = v.y - mean, dz = v.z - mean, dw = v.w - mean;
    float ss = dx * dx + dy * dy + dz * dz + dw * dw;
#pragma unroll
    for (int o = 16; o > 0; o >>= 1) ss += __shfl_xor_sync(0xffffffffu, ss, o);
    __syncthreads();
    if ((t & 31) == 0) red[t >> 5] = ss;
    __syncthreads();
    float tss = 0.f;
#pragma unroll
    for (int i = 0; i < 8; i++) tss += red[i];

    float inv = 1.0f / (sqrtf(tss * (1.0f / (DIM - 1))) + EPS);

    float4 gv = *(const float4*)(gamma + t * 4);
    float4 bv = *(const float4*)(beta + t * 4);
    float4 yv;
    yv.x = gv.x * dx * inv + bv.x;
    yv.y = gv.y * dy * inv + bv.y;
    yv.z = gv.z * dz * inv + bv.z;
    yv.w = gv.w * dw * inv + bv.w;
    *(float4*)(y + (size_t)row * DIM + t * 4) = yv;
}

// =====================================================================
// fp32 SIMT GEMM: C[M,N] = A[M,K] @ B[K,N]  (+bias)(+relu)(+residual)
// BM=BN=128, BK=8, 256 threads, 8x8 per-thread micro-tile
// =====================================================================
template <bool BIAS, bool RELU, bool RES>
__global__ void __launch_bounds__(256) gemm_kernel(
    const float* __restrict__ A, const float* __restrict__ B,
    const float* __restrict__ bias, const float* __restrict__ res,
    float* __restrict__ C, int M, int N, int K)
{
    __shared__ float As[8][128];
    __shared__ float Bs[8][128];

    int tid = threadIdx.x;
    int tx = tid & 15;          // 0..15 -> cols
    int ty = tid >> 4;          // 0..15 -> rows
    int bm = blockIdx.y * 128;
    int bn = blockIdx.x * 128;

    int arow = tid >> 1;            // 0..127
    int acol = (tid & 1) * 4;       // 0 or 4
    int brow = tid >> 5;            // 0..7
    int bcol = (tid & 31) * 4;      // 0..124

    const float* Aptr = A + (size_t)(bm + arow) * K + acol;
    const float* Bptr = B + (size_t)brow * N + bn + bcol;

    float acc[8][8];
#pragma unroll
    for (int i = 0; i < 8; i++)
#pragma unroll
        for (int j = 0; j < 8; j++) acc[i][j] = 0.f;

    for (int k0 = 0; k0 < K; k0 += 8) {
        float4 av = *(const float4*)(Aptr + k0);
        float4 bv = *(const float4*)(Bptr + (size_t)k0 * N);
        As[acol + 0][arow] = av.x;
        As[acol + 1][arow] = av.y;
        As[acol + 2][arow] = av.z;
        As[acol + 3][arow] = av.w;
        *(float4*)&Bs[brow][bcol] = bv;
        __syncthreads();

#pragma unroll
        for (int k = 0; k < 8; k++) {
            float4 a0 = *(const float4*)&As[k][ty * 8];
            float4 a1 = *(const float4*)&As[k][ty * 8 + 4];
            float4 b0 = *(const float4*)&Bs[k][tx * 8];
            float4 b1 = *(const float4*)&Bs[k][tx * 8 + 4];
            float a[8] = {a0.x, a0.y, a0.z, a0.w, a1.x, a1.y, a1.z, a1.w};
            float b[8] = {b0.x, b0.y, b0.z, b0.w, b1.x, b1.y, b1.z, b1.w};
#pragma unroll
            for (int i = 0; i < 8; i++)
#pragma unroll
                for (int j = 0; j < 8; j++) acc[i][j] += a[i] * b[j];
        }
        __syncthreads();
    }

    // epilogue
#pragma unroll
    for (int i = 0; i < 8; i++) {
        int row = bm + ty * 8 + i;
#pragma unroll
        for (int j = 0; j < 8; j += 4) {
            int col = bn + tx * 8 + j;
            float4 v;
            v.x = acc[i][j + 0];
            v.y = acc[i][j + 1];
            v.z = acc[i][j + 2];
            v.w = acc[i][j + 3];
            if (BIAS) {
                float4 bb = *(const float4*)(bias + col);
                v.x += bb.x; v.y += bb.y; v.z += bb.z; v.w += bb.w;
            }
            if (RES) {
                float4 rr = *(const float4*)(res + (size_t)row * N + col);
                v.x += rr.x; v.y += rr.y; v.z += rr.z; v.w += rr.w;
            }
            if (RELU) {
                v.x = fmaxf(v.x, 0.f); v.y = fmaxf(v.y, 0.f);
                v.z = fmaxf(v.z, 0.f); v.w = fmaxf(v.w, 0.f);
            }
            *(float4*)(C + (size_t)row * N + col) = v;
        }
    }
}

// =====================================================================
// Flash attention (fp32). grid (SEQ/128, BATCH*HEADS), 128 threads.
// Each thread owns one query row: q[64] and o[64] in registers.
// 64-key tiles; K and V share one 16KB smem buffer; S staged in 32KB smem.
// =====================================================================
__global__ void __launch_bounds__(128) attn_kernel(
    const float* __restrict__ qkv, float* __restrict__ out)
{
    __shared__ float kv[64][64];     // 16 KB, holds K then V per tile
    __shared__ float sS[64][128];    // 32 KB, S transposed [key][query]

    int t = threadIdx.x;
    int qt = blockIdx.x;
    int bh = blockIdx.y;
    int b = bh >> 4;
    int h = bh & 15;
    int tok = qt * 128 + t;

    const float* qp = qkv + (size_t)(b * SEQ + tok) * (3 * DIM) + h * DH;
    float4 q4[16];
#pragma unroll
    for (int i = 0; i < 16; i++) {
        float4 v = *(const float4*)(qp + i * 4);
        v.x *= ATT_SCALE; v.y *= ATT_SCALE; v.z *= ATT_SCALE; v.w *= ATT_SCALE;
        q4[i] = v;
    }
    float4 o4[16];
#pragma unroll
    for (int i = 0; i < 16; i++) o4[i] = make_float4(0.f, 0.f, 0.f, 0.f);
    float m = -1e30f, l = 0.f;

    for (int kt = 0; kt < SEQ; kt += 64) {
        // ---- load K tile ----
        const float* kbase = qkv + (size_t)(b * SEQ + kt) * (3 * DIM) + DIM + h * DH;
#pragma unroll
        for (int i = 0; i < 8; i++) {
            int idx = t + i * 128;           // float4 index 0..1023
            int r = idx >> 4, c = (idx & 15) * 4;
            *(float4*)&kv[r][c] = *(const float4*)(kbase + (size_t)r * (3 * DIM) + c);
        }
        __syncthreads();

        // ---- S = q . K^T, track max ----
        float mloc = m;
        for (int j = 0; j < 64; j++) {
            float s0 = 0.f, s1 = 0.f, s2 = 0.f, s3 = 0.f;
#pragma unroll
            for (int i = 0; i < 16; i++) {
                float4 kvv = *(const float4*)&kv[j][i * 4];
                s0 += q4[i].x * kvv.x;
                s1 += q4[i].y * kvv.y;
                s2 += q4[i].z * kvv.z;
                s3 += q4[i].w * kvv.w;
            }
            float s = (s0 + s1) + (s2 + s3);
            sS[j][t] = s;
            mloc = fmaxf(mloc, s);
        }
        __syncthreads();   // everyone done reading K

        // ---- load V tile (reuse kv) ----
        const float* vbase = qkv + (size_t)(b * SEQ + kt) * (3 * DIM) + 2 * DIM + h * DH;
#pragma unroll
        for (int i = 0; i < 8; i++) {
            int idx = t + i * 128;
            int r = idx >> 4, c = (idx & 15) * 4;
            *(float4*)&kv[r][c] = *(const float4*)(vbase + (size_t)r * (3 * DIM) + c);
        }

        // ---- online softmax rescale (register-only) ----
        float resc = __expf(m - mloc);
        m = mloc;
        l *= resc;
#pragma unroll
        for (int i = 0; i < 16; i++) {
            o4[i].x *= resc; o4[i].y *= resc; o4[i].z *= resc; o4[i].w *= resc;
        }
        __syncthreads();   // V tile ready

        // ---- O += P @ V ----
        for (int j = 0; j < 64; j++) {
            float p = __expf(sS[j][t] - m);
            l += p;
#pragma unroll
            for (int i = 0; i < 16; i++) {
                float4 vv = *(const float4*)&kv[j][i * 4];
                o4[i].x += p * vv.x;
                o4[i].y += p * vv.y;
                o4[i].z += p * vv.z;
                o4[i].w += p * vv.w;
            }
        }
        __syncthreads();   // protect kv before next K load
    }

    float inv = 1.0f / l;
    float* op = out + (size_t)(b * SEQ + tok) * DIM + h * DH;
#pragma unroll
    for (int i = 0; i < 16; i++) {
        float4 v = o4[i];
        v.x *= inv; v.y *= inv; v.z *= inv; v.w *= inv;
        *(float4*)(op + i * 4) = v;
    }
}

// =====================================================================
// launch
// =====================================================================
extern "C" void kernel_launch(void* const* d_in, const int* in_sizes, int n_in,
                              void* d_out, int out_size)
{
    const float* x      = (const float*)d_in[0];
    const float* w_qkv  = (const float*)d_in[1];
    const float* w_out  = (const float*)d_in[2];
    const float* b_out  = (const float*)d_in[3];
    const float* w1     = (const float*)d_in[4];
    const float* b1     = (const float*)d_in[5];
    const float* w2     = (const float*)d_in[6];
    const float* b2     = (const float*)d_in[7];
    const float* gamma1 = (const float*)d_in[8];
    const float* beta1  = (const float*)d_in[9];
    const float* gamma2 = (const float*)d_in[10];
    const float* beta2  = (const float*)d_in[11];
    float* out = (float*)d_out;

    float *xn, *qkv, *att, *x1, *h, *ff;
    cudaGetSymbolAddress((void**)&xn,  g_xn);
    cudaGetSymbolAddress((void**)&qkv, g_qkv);
    cudaGetSymbolAddress((void**)&att, g_att);
    cudaGetSymbolAddress((void**)&x1,  g_x1);
    cudaGetSymbolAddress((void**)&h,   g_h);
    cudaGetSymbolAddress((void**)&ff,  g_ff);

    // 1) xn = LN1(x)
    ln_kernel<<<TOK, 256>>>(x, gamma1, beta1, xn);

    // 2) qkv = xn @ w_qkv           [8192 x 3072]
    gemm_kernel<false, false, false><<<dim3(3 * DIM / 128, TOK / 128), 256>>>(
        xn, w_qkv, nullptr, nullptr, qkv, TOK, 3 * DIM, DIM);

    // 3) att = attention(qkv)       [8192 x 1024]
    attn_kernel<<<dim3(SEQ / 128, BATCH * HEADS), 128>>>(qkv, att);

    // 4) x1 = x + att @ w_out + b_out
    gemm_kernel<true, false, true><<<dim3(DIM / 128, TOK / 128), 256>>>(
        att, w_out, b_out, x, x1, TOK, DIM, DIM);

    // 5) h = LN2(x1)
    ln_kernel<<<TOK, 256>>>(x1, gamma2, beta2, h);

    // 6) ff = relu(h @ w1 + b1)     [8192 x 4096]
    gemm_kernel<true, true, false><<<dim3(HID / 128, TOK / 128), 256>>>(
        h, w1, b1, nullptr, ff, TOK, HID, DIM);

    // 7) out = x1 + ff @ w2 + b2
    gemm_kernel<true, false, true><<<dim3(DIM / 128, TOK / 128), 256>>>(
        ff, w2, b2, x1, out, TOK, DIM, HID);
}

// round 2
// speedup vs baseline: 3.1830x; 3.1830x over previous
#include <cuda_runtime.h>
#include <math.h>
#include <stddef.h>
#include <stdint.h>

// ---------------- problem constants ----------------
#define BATCH   4
#define SEQ     2048
#define DIM     1024
#define HEADS   16
#define DH      64
#define HID     4096
#define TOK     (BATCH * SEQ)          // 8192
#define EPS     1e-5f
#define ATT_SCALE 0.03125f             // DIM^-0.5 = 1/32

// ---------------- scratch (no cudaMalloc allowed) ----------------
__device__ float g_xn [TOK * DIM];
__device__ float g_qkv[TOK * 3 * DIM];
__device__ float g_att[TOK * DIM];
__device__ float g_x1 [TOK * DIM];
__device__ float g_h  [TOK * DIM];
__device__ float g_ff [TOK * HID];
// tf32-rounded weight copies
__device__ float g_wqkv[DIM * 3 * DIM];
__device__ float g_wout[DIM * DIM];
__device__ float g_w1  [DIM * HID];
__device__ float g_w2  [HID * DIM];

__device__ __forceinline__ float to_tf32(float x) {
    unsigned u;
    asm("cvt.rna.tf32.f32 %0, %1;" : "=r"(u) : "f"(x));
    return __uint_as_float(u);
}

// =====================================================================
// round-copy: out[i] = tf32(in[i]), vectorized
// =====================================================================
__global__ void __launch_bounds__(256) round_copy_kernel(
    const float* __restrict__ in, float* __restrict__ out, int n4)
{
    int i = blockIdx.x * blockDim.x + threadIdx.x;
    if (i >= n4) return;
    float4 v = ((const float4*)in)[i];
    v.x = to_tf32(v.x); v.y = to_tf32(v.y);
    v.z = to_tf32(v.z); v.w = to_tf32(v.w);
    ((float4*)out)[i] = v;
}

// =====================================================================
// LayerNorm (torch semantics). Output rounded to tf32 (feeds GEMM A).
// =====================================================================
__global__ void __launch_bounds__(256) ln_kernel(
    const float* __restrict__ x, const float* __restrict__ gamma,
    const float* __restrict__ beta, float* __restrict__ y)
{
    int row = blockIdx.x;
    int t = threadIdx.x;
    const float* xr = x + (size_t)row * DIM;
    float4 v = *(const float4*)(xr + t * 4);

    __shared__ float red[8];

    float s = v.x + v.y + v.z + v.w;
#pragma unroll
    for (int o = 16; o > 0; o >>= 1) s += __shfl_xor_sync(0xffffffffu, s, o);
    if ((t & 31) == 0) red[t >> 5] = s;
    __syncthreads();
    float tot = 0.f;
#pragma unroll
    for (int i = 0; i < 8; i++) tot += red[i];
    float mean = tot * (1.0f / DIM);

    float dx = v.x - mean, dy = v.y - mean, dz = v.z - mean, dw = v.w - mean;
    float ss = dx * dx + dy * dy + dz * dz + dw * dw;
#pragma unroll
    for (int o = 16; o > 0; o >>= 1) ss += __shfl_xor_sync(0xffffffffu, ss, o);
    __syncthreads();
    if ((t & 31) == 0) red[t >> 5] = ss;
    __syncthreads();
    float tss = 0.f;
#pragma unroll
    for (int i = 0; i < 8; i++) tss += red[i];

    float inv = 1.0f / (sqrtf(tss * (1.0f / (DIM - 1))) + EPS);

    float4 gv = *(const float4*)(gamma + t * 4);
    float4 bv = *(const float4*)(beta + t * 4);
    float4 yv;
    yv.x = to_tf32(gv.x * dx * inv + bv.x);
    yv.y = to_tf32(gv.y * dy * inv + bv.y);
    yv.z = to_tf32(gv.z * dz * inv + bv.z);
    yv.w = to_tf32(gv.w * dw * inv + bv.w);
    *(float4*)(y + (size_t)row * DIM + t * 4) = yv;
}

// =====================================================================
// tf32 tensor-core GEMM: C[M,N] = A[M,K] @ B[K,N] (+bias)(+relu)(+res)(round)
// BM=BN=128, BK=32, 256 threads, warps 4x2 (32x64 warp tile)
// cp.async double-buffered. A,B must be pre-rounded to tf32 in memory.
// =====================================================================
#define AS_STRIDE 36          // 32 + 4 pad (words)
#define BS_STRIDE 136         // 128 + 8 pad (words)
#define A_BUF_FLOATS (128 * AS_STRIDE)   // 4608
#define B_BUF_FLOATS (32 * BS_STRIDE)    // 4352
#define GEMM_SMEM_BYTES ((2 * A_BUF_FLOATS + 2 * B_BUF_FLOATS) * 4)  // 71680

__device__ __forceinline__ void cp16(unsigned dst, const void* src) {
    asm volatile("cp.async.cg.shared.global [%0], [%1], 16;" :: "r"(dst), "l"(src));
}
__device__ __forceinline__ void cp_commit() {
    asm volatile("cp.async.commit_group;" ::: "memory");
}
__device__ __forceinline__ void cp_wait1() {
    asm volatile("cp.async.wait_group 1;" ::: "memory");
}
__device__ __forceinline__ void cp_wait0() {
    asm volatile("cp.async.wait_group 0;" ::: "memory");
}

__device__ __forceinline__ void mma_tf32(
    float* c, const unsigned* a, const unsigned* b)
{
    asm volatile(
        "mma.sync.aligned.m16n8k8.row.col.f32.tf32.tf32.f32 "
        "{%0,%1,%2,%3}, {%4,%5,%6,%7}, {%8,%9}, {%0,%1,%2,%3};"
        : "+f"(c[0]), "+f"(c[1]), "+f"(c[2]), "+f"(c[3])
        : "r"(a[0]), "r"(a[1]), "r"(a[2]), "r"(a[3]), "r"(b[0]), "r"(b[1]));
}

template <bool BIAS, bool RELU, bool RES, bool ROUND>
__global__ void __launch_bounds__(256, 2) gemm_tc_kernel(
    const float* __restrict__ A, const float* __restrict__ B,
    const float* __restrict__ bias, const float* __restrict__ res,
    float* __restrict__ C, int M, int N, int K)
{
    extern __shared__ float sm[];
    unsigned sbase = (unsigned)__cvta_generic_to_shared(sm);

    int tid = threadIdx.x;
    int bm = blockIdx.y * 128;
    int bn = blockIdx.x * 128;

    int warp = tid >> 5;
    int lane = tid & 31;
    int wm = (warp & 3) * 32;
    int wn = (warp >> 2) * 64;
    int gg = lane >> 2;       // group 0..7
    int cc = lane & 3;        // 0..3

    float acc[2][8][4];
#pragma unroll
    for (int f = 0; f < 2; f++)
#pragma unroll
        for (int nf = 0; nf < 8; nf++)
#pragma unroll
            for (int q = 0; q < 4; q++) acc[f][nf][q] = 0.f;

    // tile loader
    auto load_tiles = [&](int k0, int buf) {
        unsigned abase = sbase + buf * (A_BUF_FLOATS * 4);
        unsigned bbase = sbase + (2 * A_BUF_FLOATS + buf * B_BUF_FLOATS) * 4;
#pragma unroll
        for (int j = 0; j < 4; j++) {
            int i = tid + j * 256;
            int m = i >> 3, c4 = (i & 7) * 4;
            cp16(abase + (m * AS_STRIDE + c4) * 4,
                 A + (size_t)(bm + m) * K + k0 + c4);
        }
#pragma unroll
        for (int j = 0; j < 4; j++) {
            int i = tid + j * 256;
            int k = i >> 5, n4 = (i & 31) * 4;
            cp16(bbase + (k * BS_STRIDE + n4) * 4,
                 B + (size_t)(k0 + k) * N + bn + n4);
        }
        cp_commit();
    };

    int T = K >> 5;     // K / 32
    load_tiles(0, 0);

    for (int t = 0; t < T; t++) {
        if (t + 1 < T) {
            load_tiles((t + 1) << 5, (t + 1) & 1);
            cp_wait1();
        } else {
            cp_wait0();
        }
        __syncthreads();

        const float* as = sm + (t & 1) * A_BUF_FLOATS;
        const float* bs = sm + 2 * A_BUF_FLOATS + (t & 1) * B_BUF_FLOATS;

#pragma unroll
        for (int ks = 0; ks < 4; ks++) {
            int kb = ks * 8;
            unsigned a[2][4], b[8][2];
#pragma unroll
            for (int f = 0; f < 2; f++) {
                int r = wm + f * 16 + gg;
                a[f][0] = __float_as_uint(as[r * AS_STRIDE + kb + cc]);
                a[f][1] = __float_as_uint(as[(r + 8) * AS_STRIDE + kb + cc]);
                a[f][2] = __float_as_uint(as[r * AS_STRIDE + kb + cc + 4]);
                a[f][3] = __float_as_uint(as[(r + 8) * AS_STRIDE + kb + cc + 4]);
            }
#pragma unroll
            for (int nf = 0; nf < 8; nf++) {
                int col = wn + nf * 8 + gg;
                b[nf][0] = __float_as_uint(bs[(kb + cc) * BS_STRIDE + col]);
                b[nf][1] = __float_as_uint(bs[(kb + cc + 4) * BS_STRIDE + col]);
            }
#pragma unroll
            for (int f = 0; f < 2; f++)
#pragma unroll
                for (int nf = 0; nf < 8; nf++)
                    mma_tf32(acc[f][nf], a[f], b[nf]);
        }
        __syncthreads();
    }

    // epilogue
#pragma unroll
    for (int f = 0; f < 2; f++) {
#pragma unroll
        for (int nf = 0; nf < 8; nf++) {
            int col = bn + wn + nf * 8 + 2 * cc;
#pragma unroll
            for (int half = 0; half < 2; half++) {
                int row = bm + wm + f * 16 + gg + half * 8;
                float v0 = acc[f][nf][half * 2 + 0];
                float v1 = acc[f][nf][half * 2 + 1];
                if (BIAS) { v0 += bias[col]; v1 += bias[col + 1]; }
                if (RES) {
                    const float* rp = res + (size_t)row * N + col;
                    v0 += rp[0]; v1 += rp[1];
                }
                if (RELU) { v0 = fmaxf(v0, 0.f); v1 = fmaxf(v1, 0.f); }
                if (ROUND) { v0 = to_tf32(v0); v1 = to_tf32(v1); }
                float2 w; w.x = v0; w.y = v1;
                *(float2*)(C + (size_t)row * N + col) = w;
            }
        }
    }
}

// =====================================================================
// Flash attention (fp32), output rounded to tf32 (feeds out-proj GEMM).
// =====================================================================
__global__ void __launch_bounds__(128) attn_kernel(
    const float* __restrict__ qkv, float* __restrict__ out)
{
    __shared__ float kv[64][64];
    __shared__ float sS[64][128];

    int t = threadIdx.x;
    int qt = blockIdx.x;
    int bh = blockIdx.y;
    int b = bh >> 4;
    int h = bh & 15;
    int tok = qt * 128 + t;

    const float* qp = qkv + (size_t)(b * SEQ + tok) * (3 * DIM) + h * DH;
    float4 q4[16];
#pragma unroll
    for (int i = 0; i < 16; i++) {
        float4 v = *(const float4*)(qp + i * 4);
        v.x *= ATT_SCALE; v.y *= ATT_SCALE; v.z *= ATT_SCALE; v.w *= ATT_SCALE;
        q4[i] = v;
    }
    float4 o4[16];
#pragma unroll
    for (int i = 0; i < 16; i++) o4[i] = make_float4(0.f, 0.f, 0.f, 0.f);
    float m = -1e30f, l = 0.f;

    for (int kt = 0; kt < SEQ; kt += 64) {
        const float* kbase = qkv + (size_t)(b * SEQ + kt) * (3 * DIM) + DIM + h * DH;
#pragma unroll
        for (int i = 0; i < 8; i++) {
            int idx = t + i * 128;
            int r = idx >> 4, c = (idx & 15) * 4;
            *(float4*)&kv[r][c] = *(const float4*)(kbase + (size_t)r * (3 * DIM) + c);
        }
        __syncthreads();

        float mloc = m;
        for (int j = 0; j < 64; j++) {
            float s0 = 0.f, s1 = 0.f, s2 = 0.f, s3 = 0.f;
#pragma unroll
            for (int i = 0; i < 16; i++) {
                float4 kvv = *(const float4*)&kv[j][i * 4];
                s0 += q4[i].x * kvv.x;
                s1 += q4[i].y * kvv.y;
                s2 += q4[i].z * kvv.z;
                s3 += q4[i].w * kvv.w;
            }
            float s = (s0 + s1) + (s2 + s3);
            sS[j][t] = s;
            mloc = fmaxf(mloc, s);
        }
        __syncthreads();

        const float* vbase = qkv + (size_t)(b * SEQ + kt) * (3 * DIM) + 2 * DIM + h * DH;
#pragma unroll
        for (int i = 0; i < 8; i++) {
            int idx = t + i * 128;
            int r = idx >> 4, c = (idx & 15) * 4;
            *(float4*)&kv[r][c] = *(const float4*)(vbase + (size_t)r * (3 * DIM) + c);
        }

        float resc = __expf(m - mloc);
        m = mloc;
        l *= resc;
#pragma unroll
        for (int i = 0; i < 16; i++) {
            o4[i].x *= resc; o4[i].y *= resc; o4[i].z *= resc; o4[i].w *= resc;
        }
        __syncthreads();

        for (int j = 0; j < 64; j++) {
            float p = __expf(sS[j][t] - m);
            l += p;
#pragma unroll
            for (int i = 0; i < 16; i++) {
                float4 vv = *(const float4*)&kv[j][i * 4];
                o4[i].x += p * vv.x;
                o4[i].y += p * vv.y;
                o4[i].z += p * vv.z;
                o4[i].w += p * vv.w;
            }
        }
        __syncthreads();
    }

    float inv = 1.0f / l;
    float* op = out + (size_t)(b * SEQ + tok) * DIM + h * DH;
#pragma unroll
    for (int i = 0; i < 16; i++) {
        float4 v = o4[i];
        v.x = to_tf32(v.x * inv);
        v.y = to_tf32(v.y * inv);
        v.z = to_tf32(v.z * inv);
        v.w = to_tf32(v.w * inv);
        *(float4*)(op + i * 4) = v;
    }
}

// =====================================================================
// launch
// =====================================================================
extern "C" void kernel_launch(void* const* d_in, const int* in_sizes, int n_in,
                              void* d_out, int out_size)
{
    const float* x      = (const float*)d_in[0];
    const float* w_qkv  = (const float*)d_in[1];
    const float* w_out  = (const float*)d_in[2];
    const float* b_out  = (const float*)d_in[3];
    const float* w1     = (const float*)d_in[4];
    const float* b1     = (const float*)d_in[5];
    const float* w2     = (const float*)d_in[6];
    const float* b2     = (const float*)d_in[7];
    const float* gamma1 = (const float*)d_in[8];
    const float* beta1  = (const float*)d_in[9];
    const float* gamma2 = (const float*)d_in[10];
    const float* beta2  = (const float*)d_in[11];
    float* out = (float*)d_out;

    float *xn, *qkv, *att, *x1, *h, *ff, *wqkv, *wout, *w1r, *w2r;
    cudaGetSymbolAddress((void**)&xn,   g_xn);
    cudaGetSymbolAddress((void**)&qkv,  g_qkv);
    cudaGetSymbolAddress((void**)&att,  g_att);
    cudaGetSymbolAddress((void**)&x1,   g_x1);
    cudaGetSymbolAddress((void**)&h,    g_h);
    cudaGetSymbolAddress((void**)&ff,   g_ff);
    cudaGetSymbolAddress((void**)&wqkv, g_wqkv);
    cudaGetSymbolAddress((void**)&wout, g_wout);
    cudaGetSymbolAddress((void**)&w1r,  g_w1);
    cudaGetSymbolAddress((void**)&w2r,  g_w2);

    // allow 70KB dynamic smem on the GEMM instantiations (idempotent)
    static bool attr_done = false;
    if (!attr_done) {
        cudaFuncSetAttribute(gemm_tc_kernel<false, false, false, false>,
                             cudaFuncAttributeMaxDynamicSharedMemorySize, GEMM_SMEM_BYTES);
        cudaFuncSetAttribute(gemm_tc_kernel<true, false, true, false>,
                             cudaFuncAttributeMaxDynamicSharedMemorySize, GEMM_SMEM_BYTES);
        cudaFuncSetAttribute(gemm_tc_kernel<true, true, false, true>,
                             cudaFuncAttributeMaxDynamicSharedMemorySize, GEMM_SMEM_BYTES);
        attr_done = true;
    }

    // 0) round weights to tf32 copies
    {
        int n4;
        n4 = DIM * 3 * DIM / 4;
        round_copy_kernel<<<(n4 + 255) / 256, 256>>>(w_qkv, wqkv, n4);
        n4 = DIM * DIM / 4;
        round_copy_kernel<<<(n4 + 255) / 256, 256>>>(w_out, wout, n4);
        n4 = DIM * HID / 4;
        round_copy_kernel<<<(n4 + 255) / 256, 256>>>(w1, w1r, n4);
        n4 = HID * DIM / 4;
        round_copy_kernel<<<(n4 + 255) / 256, 256>>>(w2, w2r, n4);
    }

    // 1) xn = tf32(LN1(x))
    ln_kernel<<<TOK, 256>>>(x, gamma1, beta1, xn);

    // 2) qkv = xn @ wqkv
    gemm_tc_kernel<false, false, false, false>
        <<<dim3(3 * DIM / 128, TOK / 128), 256, GEMM_SMEM_BYTES>>>(
        xn, wqkv, nullptr, nullptr, qkv, TOK, 3 * DIM, DIM);

    // 3) att = tf32(attention(qkv))
    attn_kernel<<<dim3(SEQ / 128, BATCH * HEADS), 128>>>(qkv, att);

    // 4) x1 = x + att @ wout + b_out
    gemm_tc_kernel<true, false, true, false>
        <<<dim3(DIM / 128, TOK / 128), 256, GEMM_SMEM_BYTES>>>(
        att, wout, b_out, x, x1, TOK, DIM, DIM);

    // 5) h = tf32(LN2(x1))
    ln_kernel<<<TOK, 256>>>(x1, gamma2, beta2, h);

    // 6) ff = tf32(relu(h @ w1 + b1))
    gemm_tc_kernel<true, true, false, true>
        <<<dim3(HID / 128, TOK / 128), 256, GEMM_SMEM_BYTES>>>(
        h, w1r, b1, nullptr, ff, TOK, HID, DIM);

    // 7) out = x1 + ff @ w2 + b2
    gemm_tc_kernel<true, false, true, false>
        <<<dim3(DIM / 128, TOK / 128), 256, GEMM_SMEM_BYTES>>>(
        ff, w2r, b2, x1, out, TOK, DIM, HID);
}

// round 3
// speedup vs baseline: 6.6912x; 2.1021x over previous
#include <cuda_runtime.h>
#include <math.h>
#include <stddef.h>
#include <stdint.h>

// ---------------- problem constants ----------------
#define BATCH   4
#define SEQ     2048
#define DIM     1024
#define HEADS   16
#define DH      64
#define HID     4096
#define TOK     (BATCH * SEQ)          // 8192
#define EPS     1e-5f
#define ATT_SCALE 0.03125f             // DIM^-0.5 = 1/32 (power of 2: exact)

// ---------------- scratch (no cudaMalloc allowed) ----------------
__device__ float g_xn [TOK * DIM];
__device__ float g_qkv[TOK * 3 * DIM];
__device__ float g_att[TOK * DIM];
__device__ float g_x1 [TOK * DIM];
__device__ float g_h  [TOK * DIM];
__device__ float g_ff [TOK * HID];
__device__ float g_wqkv[DIM * 3 * DIM];
__device__ float g_wout[DIM * DIM];
__device__ float g_w1  [DIM * HID];
__device__ float g_w2  [HID * DIM];

__device__ __forceinline__ float to_tf32(float x) {
    unsigned u;
    asm("cvt.rna.tf32.f32 %0, %1;" : "=r"(u) : "f"(x));
    return __uint_as_float(u);
}

__device__ __forceinline__ void cp16(unsigned dst, const void* src) {
    asm volatile("cp.async.cg.shared.global [%0], [%1], 16;" :: "r"(dst), "l"(src));
}
__device__ __forceinline__ void cp_commit() {
    asm volatile("cp.async.commit_group;" ::: "memory");
}
__device__ __forceinline__ void cp_wait1() {
    asm volatile("cp.async.wait_group 1;" ::: "memory");
}
__device__ __forceinline__ void cp_wait0() {
    asm volatile("cp.async.wait_group 0;" ::: "memory");
}

__device__ __forceinline__ void mma_tf32(
    float* c, const unsigned* a, const unsigned* b)
{
    asm volatile(
        "mma.sync.aligned.m16n8k8.row.col.f32.tf32.tf32.f32 "
        "{%0,%1,%2,%3}, {%4,%5,%6,%7}, {%8,%9}, {%0,%1,%2,%3};"
        : "+f"(c[0]), "+f"(c[1]), "+f"(c[2]), "+f"(c[3])
        : "r"(a[0]), "r"(a[1]), "r"(a[2]), "r"(a[3]), "r"(b[0]), "r"(b[1]));
}

// =====================================================================
// round-copy: out[i] = tf32(in[i])
// =====================================================================
__global__ void __launch_bounds__(256) round_copy_kernel(
    const float* __restrict__ in, float* __restrict__ out, int n4)
{
    int i = blockIdx.x * blockDim.x + threadIdx.x;
    if (i >= n4) return;
    float4 v = ((const float4*)in)[i];
    v.x = to_tf32(v.x); v.y = to_tf32(v.y);
    v.z = to_tf32(v.z); v.w = to_tf32(v.w);
    ((float4*)out)[i] = v;
}

// =====================================================================
// LayerNorm (torch semantics). Output rounded to tf32 (feeds GEMM A).
// =====================================================================
__global__ void __launch_bounds__(256) ln_kernel(
    const float* __restrict__ x, const float* __restrict__ gamma,
    const float* __restrict__ beta, float* __restrict__ y)
{
    int row = blockIdx.x;
    int t = threadIdx.x;
    const float* xr = x + (size_t)row * DIM;
    float4 v = *(const float4*)(xr + t * 4);

    __shared__ float red[8];

    float s = v.x + v.y + v.z + v.w;
#pragma unroll
    for (int o = 16; o > 0; o >>= 1) s += __shfl_xor_sync(0xffffffffu, s, o);
    if ((t & 31) == 0) red[t >> 5] = s;
    __syncthreads();
    float tot = 0.f;
#pragma unroll
    for (int i = 0; i < 8; i++) tot += red[i];
    float mean = tot * (1.0f / DIM);

    float dx = v.x - mean, dy = v.y - mean, dz = v.z - mean, dw = v.w - mean;
    float ss = dx * dx + dy * dy + dz * dz + dw * dw;
#pragma unroll
    for (int o = 16; o > 0; o >>= 1) ss += __shfl_xor_sync(0xffffffffu, ss, o);
    __syncthreads();
    if ((t & 31) == 0) red[t >> 5] = ss;
    __syncthreads();
    float tss = 0.f;
#pragma unroll
    for (int i = 0; i < 8; i++) tss += red[i];

    float inv = 1.0f / (sqrtf(tss * (1.0f / (DIM - 1))) + EPS);

    float4 gv = *(const float4*)(gamma + t * 4);
    float4 bv = *(const float4*)(beta + t * 4);
    float4 yv;
    yv.x = to_tf32(gv.x * dx * inv + bv.x);
    yv.y = to_tf32(gv.y * dy * inv + bv.y);
    yv.z = to_tf32(gv.z * dz * inv + bv.z);
    yv.w = to_tf32(gv.w * dw * inv + bv.w);
    *(float4*)(y + (size_t)row * DIM + t * 4) = yv;
}

// =====================================================================
// tf32 tensor-core GEMM (BM=BN=128, BK=32, 256 thr, cp.async dbl-buffer)
// =====================================================================
#define AS_STRIDE 36
#define BS_STRIDE 136
#define A_BUF_FLOATS (128 * AS_STRIDE)
#define B_BUF_FLOATS (32 * BS_STRIDE)
#define GEMM_SMEM_BYTES ((2 * A_BUF_FLOATS + 2 * B_BUF_FLOATS) * 4)  // 71680

template <bool BIAS, bool RELU, bool RES, bool ROUND>
__global__ void __launch_bounds__(256, 2) gemm_tc_kernel(
    const float* __restrict__ A, const float* __restrict__ B,
    const float* __restrict__ bias, const float* __restrict__ res,
    float* __restrict__ C, int M, int N, int K)
{
    extern __shared__ float sm[];
    unsigned sbase = (unsigned)__cvta_generic_to_shared(sm);

    int tid = threadIdx.x;
    int bm = blockIdx.y * 128;
    int bn = blockIdx.x * 128;

    int warp = tid >> 5;
    int lane = tid & 31;
    int wm = (warp & 3) * 32;
    int wn = (warp >> 2) * 64;
    int gg = lane >> 2;
    int cc = lane & 3;

    float acc[2][8][4];
#pragma unroll
    for (int f = 0; f < 2; f++)
#pragma unroll
        for (int nf = 0; nf < 8; nf++)
#pragma unroll
            for (int q = 0; q < 4; q++) acc[f][nf][q] = 0.f;

    auto load_tiles = [&](int k0, int buf) {
        unsigned abase = sbase + buf * (A_BUF_FLOATS * 4);
        unsigned bbase = sbase + (2 * A_BUF_FLOATS + buf * B_BUF_FLOATS) * 4;
#pragma unroll
        for (int j = 0; j < 4; j++) {
            int i = tid + j * 256;
            int m = i >> 3, c4 = (i & 7) * 4;
            cp16(abase + (m * AS_STRIDE + c4) * 4,
                 A + (size_t)(bm + m) * K + k0 + c4);
        }
#pragma unroll
        for (int j = 0; j < 4; j++) {
            int i = tid + j * 256;
            int k = i >> 5, n4 = (i & 31) * 4;
            cp16(bbase + (k * BS_STRIDE + n4) * 4,
                 B + (size_t)(k0 + k) * N + bn + n4);
        }
        cp_commit();
    };

    int T = K >> 5;
    load_tiles(0, 0);

    for (int t = 0; t < T; t++) {
        if (t + 1 < T) {
            load_tiles((t + 1) << 5, (t + 1) & 1);
            cp_wait1();
        } else {
            cp_wait0();
        }
        __syncthreads();

        const float* as = sm + (t & 1) * A_BUF_FLOATS;
        const float* bs = sm + 2 * A_BUF_FLOATS + (t & 1) * B_BUF_FLOATS;

#pragma unroll
        for (int ks = 0; ks < 4; ks++) {
            int kb = ks * 8;
            unsigned a[2][4], b[8][2];
#pragma unroll
            for (int f = 0; f < 2; f++) {
                int r = wm + f * 16 + gg;
                a[f][0] = __float_as_uint(as[r * AS_STRIDE + kb + cc]);
                a[f][1] = __float_as_uint(as[(r + 8) * AS_STRIDE + kb + cc]);
                a[f][2] = __float_as_uint(as[r * AS_STRIDE + kb + cc + 4]);
                a[f][3] = __float_as_uint(as[(r + 8) * AS_STRIDE + kb + cc + 4]);
            }
#pragma unroll
            for (int nf = 0; nf < 8; nf++) {
                int col = wn + nf * 8 + gg;
                b[nf][0] = __float_as_uint(bs[(kb + cc) * BS_STRIDE + col]);
                b[nf][1] = __float_as_uint(bs[(kb + cc + 4) * BS_STRIDE + col]);
            }
#pragma unroll
            for (int f = 0; f < 2; f++)
#pragma unroll
                for (int nf = 0; nf < 8; nf++)
                    mma_tf32(acc[f][nf], a[f], b[nf]);
        }
        __syncthreads();
    }

#pragma unroll
    for (int f = 0; f < 2; f++) {
#pragma unroll
        for (int nf = 0; nf < 8; nf++) {
            int col = bn + wn + nf * 8 + 2 * cc;
#pragma unroll
            for (int half = 0; half < 2; half++) {
                int row = bm + wm + f * 16 + gg + half * 8;
                float v0 = acc[f][nf][half * 2 + 0];
                float v1 = acc[f][nf][half * 2 + 1];
                if (BIAS) { v0 += bias[col]; v1 += bias[col + 1]; }
                if (RES) {
                    const float* rp = res + (size_t)row * N + col;
                    v0 += rp[0]; v1 += rp[1];
                }
                if (RELU) { v0 = fmaxf(v0, 0.f); v1 = fmaxf(v1, 0.f); }
                if (ROUND) { v0 = to_tf32(v0); v1 = to_tf32(v1); }
                float2 w; w.x = v0; w.y = v1;
                *(float2*)(C + (size_t)row * N + col) = w;
            }
        }
    }
}

// =====================================================================
// Tensor-core flash attention (tf32 mma, fp32 softmax).
// grid (SEQ/128, BATCH*HEADS), 256 threads = 8 warps, 16 q-rows/warp.
// K tiles of 64 keys, cp.async double-buffered.
// smem: K[2] + V[2] (64x68 each) + P (128x68) = 104448 B dynamic.
// =====================================================================
#define KV_STRIDE 68
#define KV_FLOATS (64 * KV_STRIDE)            // 4352
#define P_STRIDE  68
#define ATT_SMEM_BYTES ((4 * KV_FLOATS + 128 * P_STRIDE) * 4)   // 104448

__global__ void __launch_bounds__(256) attn_tc_kernel(
    const float* __restrict__ qkv, float* __restrict__ out)
{
    extern __shared__ float sm[];
    unsigned sbase = (unsigned)__cvta_generic_to_shared(sm);
    float* Ps = sm + 4 * KV_FLOATS;

    int tid = threadIdx.x;
    int warp = tid >> 5;
    int lane = tid & 31;
    int gg = lane >> 2;
    int cc = lane & 3;
    int wm = warp * 16;

    int bh = blockIdx.y;
    int b = bh >> 4;
    int h = bh & 15;
    size_t tokbase = (size_t)b * SEQ + blockIdx.x * 128;
    const float* qbase = qkv + tokbase * (3 * DIM) + h * DH;

    // --- cp.async loader for K/V tile kt (64 keys) into buffer buf ---
    auto load_kv = [&](int kt, int buf) {
        const float* kb = qkv + ((size_t)b * SEQ + kt) * (3 * DIM) + DIM + h * DH;
        const float* vb = kb + DIM;
        unsigned kdst = sbase + buf * (KV_FLOATS * 4);
        unsigned vdst = sbase + (2 + buf) * (KV_FLOATS * 4);
#pragma unroll
        for (int j = 0; j < 4; j++) {
            int idx = tid + j * 256;          // 1024 float4 per tile
            int r = idx >> 4, c4 = (idx & 15) * 4;
            cp16(kdst + (r * KV_STRIDE + c4) * 4, kb + (size_t)r * (3 * DIM) + c4);
        }
#pragma unroll
        for (int j = 0; j < 4; j++) {
            int idx = tid + j * 256;
            int r = idx >> 4, c4 = (idx & 15) * 4;
            cp16(vdst + (r * KV_STRIDE + c4) * 4, vb + (size_t)r * (3 * DIM) + c4);
        }
        cp_commit();
    };

    load_kv(0, 0);

    // --- stage Q into Ps, extract A-fragments (scaled; scale is exact) ---
#pragma unroll
    for (int j = 0; j < 8; j++) {
        int idx = tid + j * 256;              // 2048 float4
        int r = idx >> 4, c4 = (idx & 15) * 4;
        *(float4*)&Ps[r * P_STRIDE + c4] = *(const float4*)(qbase + (size_t)r * (3 * DIM) + c4);
    }
    __syncthreads();
    unsigned qf[8][4];
#pragma unroll
    for (int kf = 0; kf < 8; kf++) {
        int c0 = kf * 8 + cc;
        qf[kf][0] = __float_as_uint(Ps[(wm + gg) * P_STRIDE + c0] * ATT_SCALE);
        qf[kf][1] = __float_as_uint(Ps[(wm + gg + 8) * P_STRIDE + c0] * ATT_SCALE);
        qf[kf][2] = __float_as_uint(Ps[(wm + gg) * P_STRIDE + c0 + 4] * ATT_SCALE);
        qf[kf][3] = __float_as_uint(Ps[(wm + gg + 8) * P_STRIDE + c0 + 4] * ATT_SCALE);
    }
    __syncthreads();

    float of[8][4];
#pragma unroll
    for (int nf = 0; nf < 8; nf++)
#pragma unroll
        for (int q = 0; q < 4; q++) of[nf][q] = 0.f;
    float m0 = -1e30f, m1 = -1e30f, l0 = 0.f, l1 = 0.f;

    for (int t = 0; t < SEQ / 64; t++) {
        if (t + 1 < SEQ / 64) { load_kv((t + 1) * 64, (t + 1) & 1); cp_wait1(); }
        else cp_wait0();
        __syncthreads();

        const float* K = sm + (t & 1) * KV_FLOATS;
        const float* V = sm + (2 + (t & 1)) * KV_FLOATS;

        // ---- S = Q K^T ----
        float s[8][4];
#pragma unroll
        for (int nf = 0; nf < 8; nf++) {
#pragma unroll
            for (int q = 0; q < 4; q++) s[nf][q] = 0.f;
#pragma unroll
            for (int kf = 0; kf < 8; kf++) {
                unsigned bfr[2];
                bfr[0] = __float_as_uint(K[(nf * 8 + gg) * KV_STRIDE + kf * 8 + cc]);
                bfr[1] = __float_as_uint(K[(nf * 8 + gg) * KV_STRIDE + kf * 8 + cc + 4]);
                mma_tf32(s[nf], qf[kf], bfr);
            }
        }

        // ---- online softmax ----
        float rmax0 = -1e30f, rmax1 = -1e30f;
#pragma unroll
        for (int nf = 0; nf < 8; nf++) {
            rmax0 = fmaxf(rmax0, fmaxf(s[nf][0], s[nf][1]));
            rmax1 = fmaxf(rmax1, fmaxf(s[nf][2], s[nf][3]));
        }
        rmax0 = fmaxf(rmax0, __shfl_xor_sync(0xffffffffu, rmax0, 1));
        rmax0 = fmaxf(rmax0, __shfl_xor_sync(0xffffffffu, rmax0, 2));
        rmax1 = fmaxf(rmax1, __shfl_xor_sync(0xffffffffu, rmax1, 1));
        rmax1 = fmaxf(rmax1, __shfl_xor_sync(0xffffffffu, rmax1, 2));

        float mn0 = fmaxf(m0, rmax0);
        float mn1 = fmaxf(m1, rmax1);
        float f0 = __expf(m0 - mn0);
        float f1 = __expf(m1 - mn1);
        m0 = mn0; m1 = mn1;

        float rs0 = 0.f, rs1 = 0.f;
#pragma unroll
        for (int nf = 0; nf < 8; nf++) {
            float p0 = __expf(s[nf][0] - mn0);
            float p1 = __expf(s[nf][1] - mn0);
            float p2 = __expf(s[nf][2] - mn1);
            float p3 = __expf(s[nf][3] - mn1);
            rs0 += p0 + p1;
            rs1 += p2 + p3;
            int c0 = nf * 8 + 2 * cc;
            *(float2*)&Ps[(wm + gg) * P_STRIDE + c0]     = make_float2(to_tf32(p0), to_tf32(p1));
            *(float2*)&Ps[(wm + gg + 8) * P_STRIDE + c0] = make_float2(to_tf32(p2), to_tf32(p3));
        }
        rs0 += __shfl_xor_sync(0xffffffffu, rs0, 1);
        rs0 += __shfl_xor_sync(0xffffffffu, rs0, 2);
        rs1 += __shfl_xor_sync(0xffffffffu, rs1, 1);
        rs1 += __shfl_xor_sync(0xffffffffu, rs1, 2);
        l0 = l0 * f0 + rs0;
        l1 = l1 * f1 + rs1;

#pragma unroll
        for (int nf = 0; nf < 8; nf++) {
            of[nf][0] *= f0; of[nf][1] *= f0;
            of[nf][2] *= f1; of[nf][3] *= f1;
        }
        __syncwarp();

        // ---- O += P V ----
#pragma unroll
        for (int kf = 0; kf < 8; kf++) {
            unsigned a[4];
            int c0 = kf * 8 + cc;
            a[0] = __float_as_uint(Ps[(wm + gg) * P_STRIDE + c0]);
            a[1] = __float_as_uint(Ps[(wm + gg + 8) * P_STRIDE + c0]);
            a[2] = __float_as_uint(Ps[(wm + gg) * P_STRIDE + c0 + 4]);
            a[3] = __float_as_uint(Ps[(wm + gg + 8) * P_STRIDE + c0 + 4]);
#pragma unroll
            for (int nf = 0; nf < 8; nf++) {
                unsigned bfr[2];
                bfr[0] = __float_as_uint(V[(kf * 8 + cc) * KV_STRIDE + nf * 8 + gg]);
                bfr[1] = __float_as_uint(V[(kf * 8 + cc + 4) * KV_STRIDE + nf * 8 + gg]);
                mma_tf32(of[nf], a, bfr);
            }
        }
        __syncthreads();
    }

    // ---- epilogue: O /= l, round to tf32, store ----
    float inv0 = 1.0f / l0;
    float inv1 = 1.0f / l1;
    float* op = out + tokbase * DIM + h * DH;
#pragma unroll
    for (int nf = 0; nf < 8; nf++) {
        int c0 = nf * 8 + 2 * cc;
        float2 w0, w1;
        w0.x = to_tf32(of[nf][0] * inv0); w0.y = to_tf32(of[nf][1] * inv0);
        w1.x = to_tf32(of[nf][2] * inv1); w1.y = to_tf32(of[nf][3] * inv1);
        *(float2*)(op + (size_t)(wm + gg) * DIM + c0)     = w0;
        *(float2*)(op + (size_t)(wm + gg + 8) * DIM + c0) = w1;
    }
}

// =====================================================================
// launch
// =====================================================================
extern "C" void kernel_launch(void* const* d_in, const int* in_sizes, int n_in,
                              void* d_out, int out_size)
{
    const float* x      = (const float*)d_in[0];
    const float* w_qkv  = (const float*)d_in[1];
    const float* w_out  = (const float*)d_in[2];
    const float* b_out  = (const float*)d_in[3];
    const float* w1     = (const float*)d_in[4];
    const float* b1     = (const float*)d_in[5];
    const float* w2     = (const float*)d_in[6];
    const float* b2     = (const float*)d_in[7];
    const float* gamma1 = (const float*)d_in[8];
    const float* beta1  = (const float*)d_in[9];
    const float* gamma2 = (const float*)d_in[10];
    const float* beta2  = (const float*)d_in[11];
    float* out = (float*)d_out;

    float *xn, *qkv, *att, *x1, *h, *ff, *wqkv, *wout, *w1r, *w2r;
    cudaGetSymbolAddress((void**)&xn,   g_xn);
    cudaGetSymbolAddress((void**)&qkv,  g_qkv);
    cudaGetSymbolAddress((void**)&att,  g_att);
    cudaGetSymbolAddress((void**)&x1,   g_x1);
    cudaGetSymbolAddress((void**)&h,    g_h);
    cudaGetSymbolAddress((void**)&ff,   g_ff);
    cudaGetSymbolAddress((void**)&wqkv, g_wqkv);
    cudaGetSymbolAddress((void**)&wout, g_wout);
    cudaGetSymbolAddress((void**)&w1r,  g_w1);
    cudaGetSymbolAddress((void**)&w2r,  g_w2);

    static bool attr_done = false;
    if (!attr_done) {
        cudaFuncSetAttribute(gemm_tc_kernel<false, false, false, true>,
                             cudaFuncAttributeMaxDynamicSharedMemorySize, GEMM_SMEM_BYTES);
        cudaFuncSetAttribute(gemm_tc_kernel<true, false, true, false>,
                             cudaFuncAttributeMaxDynamicSharedMemorySize, GEMM_SMEM_BYTES);
        cudaFuncSetAttribute(gemm_tc_kernel<true, true, false, true>,
                             cudaFuncAttributeMaxDynamicSharedMemorySize, GEMM_SMEM_BYTES);
        cudaFuncSetAttribute(attn_tc_kernel,
                             cudaFuncAttributeMaxDynamicSharedMemorySize, ATT_SMEM_BYTES);
        attr_done = true;
    }

    // 0) round weights to tf32 copies
    {
        int n4;
        n4 = DIM * 3 * DIM / 4;
        round_copy_kernel<<<(n4 + 255) / 256, 256>>>(w_qkv, wqkv, n4);
        n4 = DIM * DIM / 4;
        round_copy_kernel<<<(n4 + 255) / 256, 256>>>(w_out, wout, n4);
        n4 = DIM * HID / 4;
        round_copy_kernel<<<(n4 + 255) / 256, 256>>>(w1, w1r, n4);
        n4 = HID * DIM / 4;
        round_copy_kernel<<<(n4 + 255) / 256, 256>>>(w2, w2r, n4);
    }

    // 1) xn = tf32(LN1(x))
    ln_kernel<<<TOK, 256>>>(x, gamma1, beta1, xn);

    // 2) qkv = tf32(xn @ wqkv)   (rounded: feeds tensor-core attention)
    gemm_tc_kernel<false, false, false, true>
        <<<dim3(3 * DIM / 128, TOK / 128), 256, GEMM_SMEM_BYTES>>>(
        xn, wqkv, nullptr, nullptr, qkv, TOK, 3 * DIM, DIM);

    // 3) att = tf32(attention(qkv))  — tensor-core flash attention
    attn_tc_kernel<<<dim3(SEQ / 128, BATCH * HEADS), 256, ATT_SMEM_BYTES>>>(qkv, att);

    // 4) x1 = x + att @ wout + b_out
    gemm_tc_kernel<true, false, true, false>
        <<<dim3(DIM / 128, TOK / 128), 256, GEMM_SMEM_BYTES>>>(
        att, wout, b_out, x, x1, TOK, DIM, DIM);

    // 5) h = tf32(LN2(x1))
    ln_kernel<<<TOK, 256>>>(x1, gamma2, beta2, h);

    // 6) ff = tf32(relu(h @ w1 + b1))
    gemm_tc_kernel<true, true, false, true>
        <<<dim3(HID / 128, TOK / 128), 256, GEMM_SMEM_BYTES>>>(
        h, w1r, b1, nullptr, ff, TOK, HID, DIM);

    // 7) out = x1 + ff @ w2 + b2
    gemm_tc_kernel<true, false, true, false>
        <<<dim3(DIM / 128, TOK / 128), 256, GEMM_SMEM_BYTES>>>(
        ff, w2r, b2, x1, out, TOK, DIM, HID);
}

// round 4
// speedup vs baseline: 6.9357x; 1.0365x over previous
#include <cuda_runtime.h>
#include <math.h>
#include <stddef.h>
#include <stdint.h>

// ---------------- problem constants ----------------
#define BATCH   4
#define SEQ     2048
#define DIM     1024
#define HEADS   16
#define DH      64
#define HID     4096
#define TOK     (BATCH * SEQ)          // 8192
#define EPS     1e-5f
#define ATT_SCALE 0.03125f             // DIM^-0.5 = 1/32 (power of 2: exact)

// ---------------- scratch (no cudaMalloc allowed) ----------------
__device__ float g_xn [TOK * DIM];
__device__ float g_qkv[TOK * 3 * DIM];
__device__ float g_att[TOK * DIM];
__device__ float g_x1 [TOK * DIM];
__device__ float g_h  [TOK * DIM];
__device__ float g_ff [TOK * HID];
__device__ float g_wqkv[DIM * 3 * DIM];
__device__ float g_wout[DIM * DIM];
__device__ float g_w1  [DIM * HID];
__device__ float g_w2  [HID * DIM];

__device__ __forceinline__ float to_tf32(float x) {
    unsigned u;
    asm("cvt.rna.tf32.f32 %0, %1;" : "=r"(u) : "f"(x));
    return __uint_as_float(u);
}

__device__ __forceinline__ void cp16(unsigned dst, const void* src) {
    asm volatile("cp.async.cg.shared.global [%0], [%1], 16;" :: "r"(dst), "l"(src));
}
__device__ __forceinline__ void cp_commit() {
    asm volatile("cp.async.commit_group;" ::: "memory");
}
__device__ __forceinline__ void cp_wait1() {
    asm volatile("cp.async.wait_group 1;" ::: "memory");
}
__device__ __forceinline__ void cp_wait0() {
    asm volatile("cp.async.wait_group 0;" ::: "memory");
}

__device__ __forceinline__ void mma_tf32(
    float* c, const unsigned* a, const unsigned* b)
{
    asm volatile(
        "mma.sync.aligned.m16n8k8.row.col.f32.tf32.tf32.f32 "
        "{%0,%1,%2,%3}, {%4,%5,%6,%7}, {%8,%9}, {%0,%1,%2,%3};"
        : "+f"(c[0]), "+f"(c[1]), "+f"(c[2]), "+f"(c[3])
        : "r"(a[0]), "r"(a[1]), "r"(a[2]), "r"(a[3]), "r"(b[0]), "r"(b[1]));
}

// =====================================================================
// round-copy: out[i] = tf32(in[i])
// =====================================================================
__global__ void __launch_bounds__(256) round_copy_kernel(
    const float* __restrict__ in, float* __restrict__ out, int n4)
{
    int i = blockIdx.x * blockDim.x + threadIdx.x;
    if (i >= n4) return;
    float4 v = ((const float4*)in)[i];
    v.x = to_tf32(v.x); v.y = to_tf32(v.y);
    v.z = to_tf32(v.z); v.w = to_tf32(v.w);
    ((float4*)out)[i] = v;
}

// =====================================================================
// LayerNorm (torch semantics). Output rounded to tf32 (feeds GEMM A).
// =====================================================================
__global__ void __launch_bounds__(256) ln_kernel(
    const float* __restrict__ x, const float* __restrict__ gamma,
    const float* __restrict__ beta, float* __restrict__ y)
{
    int row = blockIdx.x;
    int t = threadIdx.x;
    const float* xr = x + (size_t)row * DIM;
    float4 v = *(const float4*)(xr + t * 4);

    __shared__ float red[8];

    float s = v.x + v.y + v.z + v.w;
#pragma unroll
    for (int o = 16; o > 0; o >>= 1) s += __shfl_xor_sync(0xffffffffu, s, o);
    if ((t & 31) == 0) red[t >> 5] = s;
    __syncthreads();
    float tot = 0.f;
#pragma unroll
    for (int i = 0; i < 8; i++) tot += red[i];
    float mean = tot * (1.0f / DIM);

    float dx = v.x - mean, dy = v.y - mean, dz = v.z - mean, dw = v.w - mean;
    float ss = dx * dx + dy * dy + dz * dz + dw * dw;
#pragma unroll
    for (int o = 16; o > 0; o >>= 1) ss += __shfl_xor_sync(0xffffffffu, ss, o);
    __syncthreads();
    if ((t & 31) == 0) red[t >> 5] = ss;
    __syncthreads();
    float tss = 0.f;
#pragma unroll
    for (int i = 0; i < 8; i++) tss += red[i];

    float inv = 1.0f / (sqrtf(tss * (1.0f / (DIM - 1))) + EPS);

    float4 gv = *(const float4*)(gamma + t * 4);
    float4 bv = *(const float4*)(beta + t * 4);
    float4 yv;
    yv.x = to_tf32(gv.x * dx * inv + bv.x);
    yv.y = to_tf32(gv.y * dy * inv + bv.y);
    yv.z = to_tf32(gv.z * dz * inv + bv.z);
    yv.w = to_tf32(gv.w * dw * inv + bv.w);
    *(float4*)(y + (size_t)row * DIM + t * 4) = yv;
}

// =====================================================================
// tf32 tensor-core GEMM. CTA 128x128xBK32, 128 threads = 4 warps,
// warp tile 64x64 (2x2). cp.async double-buffered. 2 CTA/SM.
// Per-slab smem traffic 64KB (was 96KB with 32x64 warps).
// =====================================================================
#define AS_STRIDE 36
#define BS_STRIDE 136
#define A_BUF_FLOATS (128 * AS_STRIDE)
#define B_BUF_FLOATS (32 * BS_STRIDE)
#define GEMM_SMEM_BYTES ((2 * A_BUF_FLOATS + 2 * B_BUF_FLOATS) * 4)  // 71680

template <bool BIAS, bool RELU, bool RES, bool ROUND>
__global__ void __launch_bounds__(128, 2) gemm_tc_kernel(
    const float* __restrict__ A, const float* __restrict__ B,
    const float* __restrict__ bias, const float* __restrict__ res,
    float* __restrict__ C, int M, int N, int K)
{
    extern __shared__ float sm[];
    unsigned sbase = (unsigned)__cvta_generic_to_shared(sm);

    int tid = threadIdx.x;
    int bm = blockIdx.y * 128;
    int bn = blockIdx.x * 128;

    int warp = tid >> 5;
    int lane = tid & 31;
    int wm = (warp & 1) * 64;
    int wn = (warp >> 1) * 64;
    int gg = lane >> 2;
    int cc = lane & 3;

    float acc[4][8][4];
#pragma unroll
    for (int f = 0; f < 4; f++)
#pragma unroll
        for (int nf = 0; nf < 8; nf++)
#pragma unroll
            for (int q = 0; q < 4; q++) acc[f][nf][q] = 0.f;

    auto load_tiles = [&](int k0, int buf) {
        unsigned abase = sbase + buf * (A_BUF_FLOATS * 4);
        unsigned bbase = sbase + (2 * A_BUF_FLOATS + buf * B_BUF_FLOATS) * 4;
#pragma unroll
        for (int j = 0; j < 8; j++) {
            int i = tid + j * 128;
            int m = i >> 3, c4 = (i & 7) * 4;
            cp16(abase + (m * AS_STRIDE + c4) * 4,
                 A + (size_t)(bm + m) * K + k0 + c4);
        }
#pragma unroll
        for (int j = 0; j < 8; j++) {
            int i = tid + j * 128;
            int k = i >> 5, n4 = (i & 31) * 4;
            cp16(bbase + (k * BS_STRIDE + n4) * 4,
                 B + (size_t)(k0 + k) * N + bn + n4);
        }
        cp_commit();
    };

    int T = K >> 5;
    load_tiles(0, 0);

    for (int t = 0; t < T; t++) {
        if (t + 1 < T) {
            load_tiles((t + 1) << 5, (t + 1) & 1);
            cp_wait1();
        } else {
            cp_wait0();
        }
        __syncthreads();

        const float* as = sm + (t & 1) * A_BUF_FLOATS;
        const float* bs = sm + 2 * A_BUF_FLOATS + (t & 1) * B_BUF_FLOATS;

#pragma unroll
        for (int ks = 0; ks < 4; ks++) {
            int kb = ks * 8;
            unsigned a[4][4], b[8][2];
#pragma unroll
            for (int f = 0; f < 4; f++) {
                int r = wm + f * 16 + gg;
                a[f][0] = __float_as_uint(as[r * AS_STRIDE + kb + cc]);
                a[f][1] = __float_as_uint(as[(r + 8) * AS_STRIDE + kb + cc]);
                a[f][2] = __float_as_uint(as[r * AS_STRIDE + kb + cc + 4]);
                a[f][3] = __float_as_uint(as[(r + 8) * AS_STRIDE + kb + cc + 4]);
            }
#pragma unroll
            for (int nf = 0; nf < 8; nf++) {
                int col = wn + nf * 8 + gg;
                b[nf][0] = __float_as_uint(bs[(kb + cc) * BS_STRIDE + col]);
                b[nf][1] = __float_as_uint(bs[(kb + cc + 4) * BS_STRIDE + col]);
            }
#pragma unroll
            for (int f = 0; f < 4; f++)
#pragma unroll
                for (int nf = 0; nf < 8; nf++)
                    mma_tf32(acc[f][nf], a[f], b[nf]);
        }
        __syncthreads();
    }

#pragma unroll
    for (int f = 0; f < 4; f++) {
#pragma unroll
        for (int nf = 0; nf < 8; nf++) {
            int col = bn + wn + nf * 8 + 2 * cc;
#pragma unroll
            for (int half = 0; half < 2; half++) {
                int row = bm + wm + f * 16 + gg + half * 8;
                float v0 = acc[f][nf][half * 2 + 0];
                float v1 = acc[f][nf][half * 2 + 1];
                if (BIAS) { v0 += bias[col]; v1 += bias[col + 1]; }
                if (RES) {
                    const float* rp = res + (size_t)row * N + col;
                    v0 += rp[0]; v1 += rp[1];
                }
                if (RELU) { v0 = fmaxf(v0, 0.f); v1 = fmaxf(v1, 0.f); }
                if (ROUND) { v0 = to_tf32(v0); v1 = to_tf32(v1); }
                float2 w; w.x = v0; w.y = v1;
                *(float2*)(C + (size_t)row * N + col) = w;
            }
        }
    }
}

// =====================================================================
// Tensor-core flash attention (tf32 mma, fp32 softmax).
// grid (SEQ/128, BATCH*HEADS), 256 threads = 8 warps, 16 q-rows/warp.
// =====================================================================
#define KV_STRIDE 68
#define KV_FLOATS (64 * KV_STRIDE)
#define P_STRIDE  68
#define ATT_SMEM_BYTES ((4 * KV_FLOATS + 128 * P_STRIDE) * 4)   // 104448

__global__ void __launch_bounds__(256) attn_tc_kernel(
    const float* __restrict__ qkv, float* __restrict__ out)
{
    extern __shared__ float sm[];
    unsigned sbase = (unsigned)__cvta_generic_to_shared(sm);
    float* Ps = sm + 4 * KV_FLOATS;

    int tid = threadIdx.x;
    int warp = tid >> 5;
    int lane = tid & 31;
    int gg = lane >> 2;
    int cc = lane & 3;
    int wm = warp * 16;

    int bh = blockIdx.y;
    int b = bh >> 4;
    int h = bh & 15;
    size_t tokbase = (size_t)b * SEQ + blockIdx.x * 128;
    const float* qbase = qkv + tokbase * (3 * DIM) + h * DH;

    auto load_kv = [&](int kt, int buf) {
        const float* kb = qkv + ((size_t)b * SEQ + kt) * (3 * DIM) + DIM + h * DH;
        const float* vb = kb + DIM;
        unsigned kdst = sbase + buf * (KV_FLOATS * 4);
        unsigned vdst = sbase + (2 + buf) * (KV_FLOATS * 4);
#pragma unroll
        for (int j = 0; j < 4; j++) {
            int idx = tid + j * 256;
            int r = idx >> 4, c4 = (idx & 15) * 4;
            cp16(kdst + (r * KV_STRIDE + c4) * 4, kb + (size_t)r * (3 * DIM) + c4);
        }
#pragma unroll
        for (int j = 0; j < 4; j++) {
            int idx = tid + j * 256;
            int r = idx >> 4, c4 = (idx & 15) * 4;
            cp16(vdst + (r * KV_STRIDE + c4) * 4, vb + (size_t)r * (3 * DIM) + c4);
        }
        cp_commit();
    };

    load_kv(0, 0);

#pragma unroll
    for (int j = 0; j < 8; j++) {
        int idx = tid + j * 256;
        int r = idx >> 4, c4 = (idx & 15) * 4;
        *(float4*)&Ps[r * P_STRIDE + c4] = *(const float4*)(qbase + (size_t)r * (3 * DIM) + c4);
    }
    __syncthreads();
    unsigned qf[8][4];
#pragma unroll
    for (int kf = 0; kf < 8; kf++) {
        int c0 = kf * 8 + cc;
        qf[kf][0] = __float_as_uint(Ps[(wm + gg) * P_STRIDE + c0] * ATT_SCALE);
        qf[kf][1] = __float_as_uint(Ps[(wm + gg + 8) * P_STRIDE + c0] * ATT_SCALE);
        qf[kf][2] = __float_as_uint(Ps[(wm + gg) * P_STRIDE + c0 + 4] * ATT_SCALE);
        qf[kf][3] = __float_as_uint(Ps[(wm + gg + 8) * P_STRIDE + c0 + 4] * ATT_SCALE);
    }
    __syncthreads();

    float of[8][4];
#pragma unroll
    for (int nf = 0; nf < 8; nf++)
#pragma unroll
        for (int q = 0; q < 4; q++) of[nf][q] = 0.f;
    float m0 = -1e30f, m1 = -1e30f, l0 = 0.f, l1 = 0.f;

    for (int t = 0; t < SEQ / 64; t++) {
        if (t + 1 < SEQ / 64) { load_kv((t + 1) * 64, (t + 1) & 1); cp_wait1(); }
        else cp_wait0();
        __syncthreads();

        const float* K = sm + (t & 1) * KV_FLOATS;
        const float* V = sm + (2 + (t & 1)) * KV_FLOATS;

        float s[8][4];
#pragma unroll
        for (int nf = 0; nf < 8; nf++) {
#pragma unroll
            for (int q = 0; q < 4; q++) s[nf][q] = 0.f;
#pragma unroll
            for (int kf = 0; kf < 8; kf++) {
                unsigned bfr[2];
                bfr[0] = __float_as_uint(K[(nf * 8 + gg) * KV_STRIDE + kf * 8 + cc]);
                bfr[1] = __float_as_uint(K[(nf * 8 + gg) * KV_STRIDE + kf * 8 + cc + 4]);
                mma_tf32(s[nf], qf[kf], bfr);
            }
        }

        float rmax0 = -1e30f, rmax1 = -1e30f;
#pragma unroll
        for (int nf = 0; nf < 8; nf++) {
            rmax0 = fmaxf(rmax0, fmaxf(s[nf][0], s[nf][1]));
            rmax1 = fmaxf(rmax1, fmaxf(s[nf][2], s[nf][3]));
        }
        rmax0 = fmaxf(rmax0, __shfl_xor_sync(0xffffffffu, rmax0, 1));
        rmax0 = fmaxf(rmax0, __shfl_xor_sync(0xffffffffu, rmax0, 2));
        rmax1 = fmaxf(rmax1, __shfl_xor_sync(0xffffffffu, rmax1, 1));
        rmax1 = fmaxf(rmax1, __shfl_xor_sync(0xffffffffu, rmax1, 2));

        float mn0 = fmaxf(m0, rmax0);
        float mn1 = fmaxf(m1, rmax1);
        float f0 = __expf(m0 - mn0);
        float f1 = __expf(m1 - mn1);
        m0 = mn0; m1 = mn1;

        float rs0 = 0.f, rs1 = 0.f;
#pragma unroll
        for (int nf = 0; nf < 8; nf++) {
            float p0 = __expf(s[nf][0] - mn0);
            float p1 = __expf(s[nf][1] - mn0);
            float p2 = __expf(s[nf][2] - mn1);
            float p3 = __expf(s[nf][3] - mn1);
            rs0 += p0 + p1;
            rs1 += p2 + p3;
            int c0 = nf * 8 + 2 * cc;
            *(float2*)&Ps[(wm + gg) * P_STRIDE + c0]     = make_float2(to_tf32(p0), to_tf32(p1));
            *(float2*)&Ps[(wm + gg + 8) * P_STRIDE + c0] = make_float2(to_tf32(p2), to_tf32(p3));
        }
        rs0 += __shfl_xor_sync(0xffffffffu, rs0, 1);
        rs0 += __shfl_xor_sync(0xffffffffu, rs0, 2);
        rs1 += __shfl_xor_sync(0xffffffffu, rs1, 1);
        rs1 += __shfl_xor_sync(0xffffffffu, rs1, 2);
        l0 = l0 * f0 + rs0;
        l1 = l1 * f1 + rs1;

#pragma unroll
        for (int nf = 0; nf < 8; nf++) {
            of[nf][0] *= f0; of[nf][1] *= f0;
            of[nf][2] *= f1; of[nf][3] *= f1;
        }
        __syncwarp();

#pragma unroll
        for (int kf = 0; kf < 8; kf++) {
            unsigned a[4];
            int c0 = kf * 8 + cc;
            a[0] = __float_as_uint(Ps[(wm + gg) * P_STRIDE + c0]);
            a[1] = __float_as_uint(Ps[(wm + gg + 8) * P_STRIDE + c0]);
            a[2] = __float_as_uint(Ps[(wm + gg) * P_STRIDE + c0 + 4]);
            a[3] = __float_as_uint(Ps[(wm + gg + 8) * P_STRIDE + c0 + 4]);
#pragma unroll
            for (int nf = 0; nf < 8; nf++) {
                unsigned bfr[2];
                bfr[0] = __float_as_uint(V[(kf * 8 + cc) * KV_STRIDE + nf * 8 + gg]);
                bfr[1] = __float_as_uint(V[(kf * 8 + cc + 4) * KV_STRIDE + nf * 8 + gg]);
                mma_tf32(of[nf], a, bfr);
            }
        }
        __syncthreads();
    }

    float inv0 = 1.0f / l0;
    float inv1 = 1.0f / l1;
    float* op = out + tokbase * DIM + h * DH;
#pragma unroll
    for (int nf = 0; nf < 8; nf++) {
        int c0 = nf * 8 + 2 * cc;
        float2 w0, w1;
        w0.x = to_tf32(of[nf][0] * inv0); w0.y = to_tf32(of[nf][1] * inv0);
        w1.x = to_tf32(of[nf][2] * inv1); w1.y = to_tf32(of[nf][3] * inv1);
        *(float2*)(op + (size_t)(wm + gg) * DIM + c0)     = w0;
        *(float2*)(op + (size_t)(wm + gg + 8) * DIM + c0) = w1;
    }
}

// =====================================================================
// launch
// =====================================================================
extern "C" void kernel_launch(void* const* d_in, const int* in_sizes, int n_in,
                              void* d_out, int out_size)
{
    const float* x      = (const float*)d_in[0];
    const float* w_qkv  = (const float*)d_in[1];
    const float* w_out  = (const float*)d_in[2];
    const float* b_out  = (const float*)d_in[3];
    const float* w1     = (const float*)d_in[4];
    const float* b1     = (const float*)d_in[5];
    const float* w2     = (const float*)d_in[6];
    const float* b2     = (const float*)d_in[7];
    const float* gamma1 = (const float*)d_in[8];
    const float* beta1  = (const float*)d_in[9];
    const float* gamma2 = (const float*)d_in[10];
    const float* beta2  = (const float*)d_in[11];
    float* out = (float*)d_out;

    float *xn, *qkv, *att, *x1, *h, *ff, *wqkv, *wout, *w1r, *w2r;
    cudaGetSymbolAddress((void**)&xn,   g_xn);
    cudaGetSymbolAddress((void**)&qkv,  g_qkv);
    cudaGetSymbolAddress((void**)&att,  g_att);
    cudaGetSymbolAddress((void**)&x1,   g_x1);
    cudaGetSymbolAddress((void**)&h,    g_h);
    cudaGetSymbolAddress((void**)&ff,   g_ff);
    cudaGetSymbolAddress((void**)&wqkv, g_wqkv);
    cudaGetSymbolAddress((void**)&wout, g_wout);
    cudaGetSymbolAddress((void**)&w1r,  g_w1);
    cudaGetSymbolAddress((void**)&w2r,  g_w2);

    static bool attr_done = false;
    if (!attr_done) {
        cudaFuncSetAttribute(gemm_tc_kernel<false, false, false, true>,
                             cudaFuncAttributeMaxDynamicSharedMemorySize, GEMM_SMEM_BYTES);
        cudaFuncSetAttribute(gemm_tc_kernel<true, false, true, false>,
                             cudaFuncAttributeMaxDynamicSharedMemorySize, GEMM_SMEM_BYTES);
        cudaFuncSetAttribute(gemm_tc_kernel<true, true, false, true>,
                             cudaFuncAttributeMaxDynamicSharedMemorySize, GEMM_SMEM_BYTES);
        cudaFuncSetAttribute(attn_tc_kernel,
                             cudaFuncAttributeMaxDynamicSharedMemorySize, ATT_SMEM_BYTES);
        attr_done = true;
    }

    // 0) round weights to tf32 copies
    {
        int n4;
        n4 = DIM * 3 * DIM / 4;
        round_copy_kernel<<<(n4 + 255) / 256, 256>>>(w_qkv, wqkv, n4);
        n4 = DIM * DIM / 4;
        round_copy_kernel<<<(n4 + 255) / 256, 256>>>(w_out, wout, n4);
        n4 = DIM * HID / 4;
        round_copy_kernel<<<(n4 + 255) / 256, 256>>>(w1, w1r, n4);
        n4 = HID * DIM / 4;
        round_copy_kernel<<<(n4 + 255) / 256, 256>>>(w2, w2r, n4);
    }

    // 1) xn = tf32(LN1(x))
    ln_kernel<<<TOK, 256>>>(x, gamma1, beta1, xn);

    // 2) qkv = tf32(xn @ wqkv)
    gemm_tc_kernel<false, false, false, true>
        <<<dim3(3 * DIM / 128, TOK / 128), 128, GEMM_SMEM_BYTES>>>(
        xn, wqkv, nullptr, nullptr, qkv, TOK, 3 * DIM, DIM);

    // 3) att = tf32(attention(qkv))
    attn_tc_kernel<<<dim3(SEQ / 128, BATCH * HEADS), 256, ATT_SMEM_BYTES>>>(qkv, att);

    // 4) x1 = x + att @ wout + b_out
    gemm_tc_kernel<true, false, true, false>
        <<<dim3(DIM / 128, TOK / 128), 128, GEMM_SMEM_BYTES>>>(
        att, wout, b_out, x, x1, TOK, DIM, DIM);

    // 5) h = tf32(LN2(x1))
    ln_kernel<<<TOK, 256>>>(x1, gamma2, beta2, h);

    // 6) ff = tf32(relu(h @ w1 + b1))
    gemm_tc_kernel<true, true, false, true>
        <<<dim3(HID / 128, TOK / 128), 128, GEMM_SMEM_BYTES>>>(
        h, w1r, b1, nullptr, ff, TOK, HID, DIM);

    // 7) out = x1 + ff @ w2 + b2
    gemm_tc_kernel<true, false, true, false>
        <<<dim3(DIM / 128, TOK / 128), 128, GEMM_SMEM_BYTES>>>(
        ff, w2r, b2, x1, out, TOK, DIM, HID);
}

// round 6
// speedup vs baseline: 9.7485x; 1.4056x over previous
#include <cuda_runtime.h>
#include <cuda_fp16.h>
#include <math.h>
#include <stddef.h>
#include <stdint.h>

// ---------------- problem constants ----------------
#define BATCH   4
#define SEQ     2048
#define DIM     1024
#define HEADS   16
#define DH      64
#define HID     4096
#define TOK     (BATCH * SEQ)          // 8192
#define EPS     1e-5f
#define ATT_SCALE 0.03125f             // DIM^-0.5 = 1/32 (power of 2: exact)

// ---------------- scratch (no cudaMalloc allowed) ----------------
__device__ __half g_xn [TOK * DIM];
__device__ float  g_qkv[TOK * 3 * DIM];
__device__ __half g_att[TOK * DIM];
__device__ float  g_x1 [TOK * DIM];
__device__ __half g_h  [TOK * DIM];
__device__ __half g_ff [TOK * HID];
// packed fp16 weights: [K/2][N] of half2 (k-pairs)
__device__ unsigned g_wqkv[(DIM / 2) * 3 * DIM];
__device__ unsigned g_wout[(DIM / 2) * DIM];
__device__ unsigned g_w1  [(DIM / 2) * HID];
__device__ unsigned g_w2  [(HID / 2) * DIM];

// ---------------- helpers ----------------
__device__ __forceinline__ float to_tf32(float x) {
    unsigned u;
    asm("cvt.rna.tf32.f32 %0, %1;" : "=r"(u) : "f"(x));
    return __uint_as_float(u);
}
__device__ __forceinline__ void cp16(unsigned dst, const void* src) {
    asm volatile("cp.async.cg.shared.global [%0], [%1], 16;" :: "r"(dst), "l"(src));
}
__device__ __forceinline__ void cp_commit() {
    asm volatile("cp.async.commit_group;" ::: "memory");
}
__device__ __forceinline__ void cp_wait1() {
    asm volatile("cp.async.wait_group 1;" ::: "memory");
}
__device__ __forceinline__ void cp_wait0() {
    asm volatile("cp.async.wait_group 0;" ::: "memory");
}

// fp16 mma, fp32 accumulate: D(16x8) += A(16x16) B(16x8)
__device__ __forceinline__ void mma_fp16(
    float* c, const unsigned* a, const unsigned* b)
{
    asm volatile(
        "mma.sync.aligned.m16n8k16.row.col.f32.f16.f16.f32 "
        "{%0,%1,%2,%3}, {%4,%5,%6,%7}, {%8,%9}, {%0,%1,%2,%3};"
        : "+f"(c[0]), "+f"(c[1]), "+f"(c[2]), "+f"(c[3])
        : "r"(a[0]), "r"(a[1]), "r"(a[2]), "r"(a[3]), "r"(b[0]), "r"(b[1]));
}
// tf32 mma (attention)
__device__ __forceinline__ void mma_tf32(
    float* c, const unsigned* a, const unsigned* b)
{
    asm volatile(
        "mma.sync.aligned.m16n8k8.row.col.f32.tf32.tf32.f32 "
        "{%0,%1,%2,%3}, {%4,%5,%6,%7}, {%8,%9}, {%0,%1,%2,%3};"
        : "+f"(c[0]), "+f"(c[1]), "+f"(c[2]), "+f"(c[3])
        : "r"(a[0]), "r"(a[1]), "r"(a[2]), "r"(a[3]), "r"(b[0]), "r"(b[1]));
}

// =====================================================================
// weight pack: out[k2][n] = half2(w[2k2][n], w[2k2+1][n])
// =====================================================================
__global__ void __launch_bounds__(256) pack_w_kernel(
    const float* __restrict__ w, unsigned* __restrict__ out, int K, int N)
{
    int n = blockIdx.x * 256 + threadIdx.x;
    int k2 = blockIdx.y;
    float lo = w[(size_t)(2 * k2) * N + n];
    float hi = w[(size_t)(2 * k2 + 1) * N + n];
    __half2 h = __floats2half2_rn(lo, hi);
    out[(size_t)k2 * N + n] = *(unsigned*)&h;
}

// =====================================================================
// LayerNorm (torch semantics), fp16 output.
// =====================================================================
__global__ void __launch_bounds__(256) ln_kernel(
    const float* __restrict__ x, const float* __restrict__ gamma,
    const float* __restrict__ beta, __half* __restrict__ y)
{
    int row = blockIdx.x;
    int t = threadIdx.x;
    const float* xr = x + (size_t)row * DIM;
    float4 v = *(const float4*)(xr + t * 4);

    __shared__ float red[8];

    float s = v.x + v.y + v.z + v.w;
#pragma unroll
    for (int o = 16; o > 0; o >>= 1) s += __shfl_xor_sync(0xffffffffu, s, o);
    if ((t & 31) == 0) red[t >> 5] = s;
    __syncthreads();
    float tot = 0.f;
#pragma unroll
    for (int i = 0; i < 8; i++) tot += red[i];
    float mean = tot * (1.0f / DIM);

    float dx = v.x - mean, dy = v.y - mean, dz = v.z - mean, dw = v.w - mean;
    float ss = dx * dx + dy * dy + dz * dz + dw * dw;
#pragma unroll
    for (int o = 16; o > 0; o >>= 1) ss += __shfl_xor_sync(0xffffffffu, ss, o);
    __syncthreads();
    if ((t & 31) == 0) red[t >> 5] = ss;
    __syncthreads();
    float tss = 0.f;
#pragma unroll
    for (int i = 0; i < 8; i++) tss += red[i];

    float inv = 1.0f / (sqrtf(tss * (1.0f / (DIM - 1))) + EPS);

    float4 gv = *(const float4*)(gamma + t * 4);
    float4 bv = *(const float4*)(beta + t * 4);
    __half2 h01 = __floats2half2_rn(gv.x * dx * inv + bv.x, gv.y * dy * inv + bv.y);
    __half2 h23 = __floats2half2_rn(gv.z * dz * inv + bv.z, gv.w * dw * inv + bv.w);
    __half2* yp = (__half2*)(y + (size_t)row * DIM + t * 4);
    yp[0] = h01;
    yp[1] = h23;
}

// =====================================================================
// fp16 tensor-core GEMM: C[M,N] = A[M,K] @ W  (+bias)(+relu)(+res)(round)
// A: fp16 [M,K] row-major.  Bp: packed half2 [K/2][N].
// BM=BN=128, BK=64 halves, 128 threads = 4 warps (64x64 warp tile).
// cp.async double-buffered.  2 CTA/SM.
// =====================================================================
#define AH_STRIDE 72                          // halves (144 B/row)
#define A_BUF_BYTES (128 * AH_STRIDE * 2)     // 18432
#define BW_STRIDE 136                         // words
#define B_BUF_BYTES (32 * BW_STRIDE * 4)      // 17408
#define GEMM_SMEM_BYTES (2 * A_BUF_BYTES + 2 * B_BUF_BYTES)   // 71680

template <typename OutT, bool BIAS, bool RELU, bool RES, bool ROUND>
__global__ void __launch_bounds__(128, 2) gemm_fp16_kernel(
    const __half* __restrict__ A, const unsigned* __restrict__ Bp,
    const float* __restrict__ bias, const float* __restrict__ res,
    OutT* __restrict__ C, int M, int N, int K)
{
    extern __shared__ char smraw[];
    unsigned sbase = (unsigned)__cvta_generic_to_shared(smraw);
    const __half* As_all = (const __half*)smraw;
    const unsigned* Bs_all = (const unsigned*)(smraw + 2 * A_BUF_BYTES);

    int tid = threadIdx.x;
    int warp = tid >> 5;
    int lane = tid & 31;
    int bm = blockIdx.y * 128;
    int bn = blockIdx.x * 128;
    int wm = (warp & 1) * 64;
    int wn = (warp >> 1) * 64;
    int gg = lane >> 2;
    int cc = lane & 3;

    float acc[4][8][4];
#pragma unroll
    for (int f = 0; f < 4; f++)
#pragma unroll
        for (int nf = 0; nf < 8; nf++)
#pragma unroll
            for (int q = 0; q < 4; q++) acc[f][nf][q] = 0.f;

    // loads: A tile 128 rows x 64 halves (8 chunks/row), B tile 32 rows x 128 words
    auto load_tiles = [&](int t, int s) {
        int k0 = t * 64;                       // halves
        unsigned abase = sbase + s * A_BUF_BYTES;
        unsigned bbase = sbase + 2 * A_BUF_BYTES + s * B_BUF_BYTES;
#pragma unroll
        for (int j = 0; j < 8; j++) {
            int idx = tid + j * 128;           // 1024 chunks
            int r = idx >> 3, c = idx & 7;
            cp16(abase + r * (AH_STRIDE * 2) + c * 16,
                 A + (size_t)(bm + r) * K + k0 + c * 8);
        }
#pragma unroll
        for (int j = 0; j < 8; j++) {
            int idx = tid + j * 128;           // 1024 chunks
            int r = idx >> 5, c4 = idx & 31;
            cp16(bbase + r * (BW_STRIDE * 4) + c4 * 16,
                 Bp + (size_t)(t * 32 + r) * N + bn + c4 * 4);
        }
        cp_commit();
    };

    int nT = K >> 6;
    load_tiles(0, 0);

    for (int t = 0; t < nT; t++) {
        if (t + 1 < nT) {
            load_tiles(t + 1, (t + 1) & 1);
            cp_wait1();
        } else {
            cp_wait0();
        }
        __syncthreads();

        const __half* as = (const __half*)((const char*)As_all + (t & 1) * A_BUF_BYTES);
        const unsigned* bs = (const unsigned*)((const char*)Bs_all + (t & 1) * B_BUF_BYTES);

#pragma unroll
        for (int ks = 0; ks < 4; ks++) {
            int kb = ks * 16;                  // halves
            unsigned a[4][4], b[8][2];
#pragma unroll
            for (int f = 0; f < 4; f++) {
                int r = wm + f * 16 + gg;
                a[f][0] = *(const unsigned*)&as[r * AH_STRIDE + kb + 2 * cc];
                a[f][1] = *(const unsigned*)&as[(r + 8) * AH_STRIDE + kb + 2 * cc];
                a[f][2] = *(const unsigned*)&as[r * AH_STRIDE + kb + 2 * cc + 8];
                a[f][3] = *(const unsigned*)&as[(r + 8) * AH_STRIDE + kb + 2 * cc + 8];
            }
#pragma unroll
            for (int nf = 0; nf < 8; nf++) {
                int col = wn + nf * 8 + gg;
                b[nf][0] = bs[(kb / 2 + cc) * BW_STRIDE + col];
                b[nf][1] = bs[(kb / 2 + cc + 4) * BW_STRIDE + col];
            }
#pragma unroll
            for (int f = 0; f < 4; f++)
#pragma unroll
                for (int nf = 0; nf < 8; nf++)
                    mma_fp16(acc[f][nf], a[f], b[nf]);
        }
        __syncthreads();
    }

    // epilogue
#pragma unroll
    for (int f = 0; f < 4; f++) {
#pragma unroll
        for (int nf = 0; nf < 8; nf++) {
            int col = bn + wn + nf * 8 + 2 * cc;
#pragma unroll
            for (int half_i = 0; half_i < 2; half_i++) {
                int row = bm + wm + f * 16 + gg + half_i * 8;
                float v0 = acc[f][nf][half_i * 2 + 0];
                float v1 = acc[f][nf][half_i * 2 + 1];
                if (BIAS) { v0 += bias[col]; v1 += bias[col + 1]; }
                if (RES) {
                    const float* rp = res + (size_t)row * N + col;
                    v0 += rp[0]; v1 += rp[1];
                }
                if (RELU) { v0 = fmaxf(v0, 0.f); v1 = fmaxf(v1, 0.f); }
                if (sizeof(OutT) == 2) {
                    __half2 hv = __floats2half2_rn(v0, v1);
                    *(__half2*)((__half*)C + (size_t)row * N + col) = hv;
                } else {
                    if (ROUND) { v0 = to_tf32(v0); v1 = to_tf32(v1); }
                    float2 w; w.x = v0; w.y = v1;
                    *(float2*)((float*)C + (size_t)row * N + col) = w;
                }
            }
        }
    }
}

// =====================================================================
// Tensor-core flash attention (tf32 mma, fp32 softmax); fp16 output.
// grid (SEQ/128, BATCH*HEADS), 256 threads = 8 warps, 16 q-rows/warp.
// =====================================================================
#define KV_STRIDE 68
#define KV_FLOATS (64 * KV_STRIDE)
#define P_STRIDE  68
#define ATT_SMEM_BYTES ((4 * KV_FLOATS + 128 * P_STRIDE) * 4)   // 104448

__global__ void __launch_bounds__(256) attn_tc_kernel(
    const float* __restrict__ qkv, __half* __restrict__ out)
{
    extern __shared__ float sm[];
    unsigned sbase = (unsigned)__cvta_generic_to_shared(sm);
    float* Ps = sm + 4 * KV_FLOATS;

    int tid = threadIdx.x;
    int warp = tid >> 5;
    int lane = tid & 31;
    int gg = lane >> 2;
    int cc = lane & 3;
    int wm = warp * 16;

    int bh = blockIdx.y;
    int b = bh >> 4;
    int h = bh & 15;
    size_t tokbase = (size_t)b * SEQ + blockIdx.x * 128;
    const float* qbase = qkv + tokbase * (3 * DIM) + h * DH;

    auto load_kv = [&](int kt, int buf) {
        const float* kb = qkv + ((size_t)b * SEQ + kt) * (3 * DIM) + DIM + h * DH;
        const float* vb = kb + DIM;
        unsigned kdst = sbase + buf * (KV_FLOATS * 4);
        unsigned vdst = sbase + (2 + buf) * (KV_FLOATS * 4);
#pragma unroll
        for (int j = 0; j < 4; j++) {
            int idx = tid + j * 256;
            int r = idx >> 4, c4 = (idx & 15) * 4;
            cp16(kdst + (r * KV_STRIDE + c4) * 4, kb + (size_t)r * (3 * DIM) + c4);
        }
#pragma unroll
        for (int j = 0; j < 4; j++) {
            int idx = tid + j * 256;
            int r = idx >> 4, c4 = (idx & 15) * 4;
            cp16(vdst + (r * KV_STRIDE + c4) * 4, vb + (size_t)r * (3 * DIM) + c4);
        }
        cp_commit();
    };

    load_kv(0, 0);

#pragma unroll
    for (int j = 0; j < 8; j++) {
        int idx = tid + j * 256;
        int r = idx >> 4, c4 = (idx & 15) * 4;
        *(float4*)&Ps[r * P_STRIDE + c4] = *(const float4*)(qbase + (size_t)r * (3 * DIM) + c4);
    }
    __syncthreads();
    unsigned qf[8][4];
#pragma unroll
    for (int kf = 0; kf < 8; kf++) {
        int c0 = kf * 8 + cc;
        qf[kf][0] = __float_as_uint(Ps[(wm + gg) * P_STRIDE + c0] * ATT_SCALE);
        qf[kf][1] = __float_as_uint(Ps[(wm + gg + 8) * P_STRIDE + c0] * ATT_SCALE);
        qf[kf][2] = __float_as_uint(Ps[(wm + gg) * P_STRIDE + c0 + 4] * ATT_SCALE);
        qf[kf][3] = __float_as_uint(Ps[(wm + gg + 8) * P_STRIDE + c0 + 4] * ATT_SCALE);
    }
    __syncthreads();

    float of[8][4];
#pragma unroll
    for (int nf = 0; nf < 8; nf++)
#pragma unroll
        for (int q = 0; q < 4; q++) of[nf][q] = 0.f;
    float m0 = -1e30f, m1 = -1e30f, l0 = 0.f, l1 = 0.f;

    for (int t = 0; t < SEQ / 64; t++) {
        if (t + 1 < SEQ / 64) { load_kv((t + 1) * 64, (t + 1) & 1); cp_wait1(); }
        else cp_wait0();
        __syncthreads();

        const float* K = sm + (t & 1) * KV_FLOATS;
        const float* V = sm + (2 + (t & 1)) * KV_FLOATS;

        float s[8][4];
#pragma unroll
        for (int nf = 0; nf < 8; nf++) {
#pragma unroll
            for (int q = 0; q < 4; q++) s[nf][q] = 0.f;
#pragma unroll
            for (int kf = 0; kf < 8; kf++) {
                unsigned bfr[2];
                bfr[0] = __float_as_uint(K[(nf * 8 + gg) * KV_STRIDE + kf * 8 + cc]);
                bfr[1] = __float_as_uint(K[(nf * 8 + gg) * KV_STRIDE + kf * 8 + cc + 4]);
                mma_tf32(s[nf], qf[kf], bfr);
            }
        }

        float rmax0 = -1e30f, rmax1 = -1e30f;
#pragma unroll
        for (int nf = 0; nf < 8; nf++) {
            rmax0 = fmaxf(rmax0, fmaxf(s[nf][0], s[nf][1]));
            rmax1 = fmaxf(rmax1, fmaxf(s[nf][2], s[nf][3]));
        }
        rmax0 = fmaxf(rmax0, __shfl_xor_sync(0xffffffffu, rmax0, 1));
        rmax0 = fmaxf(rmax0, __shfl_xor_sync(0xffffffffu, rmax0, 2));
        rmax1 = fmaxf(rmax1, __shfl_xor_sync(0xffffffffu, rmax1, 1));
        rmax1 = fmaxf(rmax1, __shfl_xor_sync(0xffffffffu, rmax1, 2));

        float mn0 = fmaxf(m0, rmax0);
        float mn1 = fmaxf(m1, rmax1);
        float f0 = __expf(m0 - mn0);
        float f1 = __expf(m1 - mn1);
        m0 = mn0; m1 = mn1;

        float rs0 = 0.f, rs1 = 0.f;
#pragma unroll
        for (int nf = 0; nf < 8; nf++) {
            float p0 = __expf(s[nf][0] - mn0);
            float p1 = __expf(s[nf][1] - mn0);
            float p2 = __expf(s[nf][2] - mn1);
            float p3 = __expf(s[nf][3] - mn1);
            rs0 += p0 + p1;
            rs1 += p2 + p3;
            int c0 = nf * 8 + 2 * cc;
            *(float2*)&Ps[(wm + gg) * P_STRIDE + c0]     = make_float2(to_tf32(p0), to_tf32(p1));
            *(float2*)&Ps[(wm + gg + 8) * P_STRIDE + c0] = make_float2(to_tf32(p2), to_tf32(p3));
        }
        rs0 += __shfl_xor_sync(0xffffffffu, rs0, 1);
        rs0 += __shfl_xor_sync(0xffffffffu, rs0, 2);
        rs1 += __shfl_xor_sync(0xffffffffu, rs1, 1);
        rs1 += __shfl_xor_sync(0xffffffffu, rs1, 2);
        l0 = l0 * f0 + rs0;
        l1 = l1 * f1 + rs1;

#pragma unroll
        for (int nf = 0; nf < 8; nf++) {
            of[nf][0] *= f0; of[nf][1] *= f0;
            of[nf][2] *= f1; of[nf][3] *= f1;
        }
        __syncwarp();

#pragma unroll
        for (int kf = 0; kf < 8; kf++) {
            unsigned a[4];
            int c0 = kf * 8 + cc;
            a[0] = __float_as_uint(Ps[(wm + gg) * P_STRIDE + c0]);
            a[1] = __float_as_uint(Ps[(wm + gg + 8) * P_STRIDE + c0]);
            a[2] = __float_as_uint(Ps[(wm + gg) * P_STRIDE + c0 + 4]);
            a[3] = __float_as_uint(Ps[(wm + gg + 8) * P_STRIDE + c0 + 4]);
#pragma unroll
            for (int nf = 0; nf < 8; nf++) {
                unsigned bfr[2];
                bfr[0] = __float_as_uint(V[(kf * 8 + cc) * KV_STRIDE + nf * 8 + gg]);
                bfr[1] = __float_as_uint(V[(kf * 8 + cc + 4) * KV_STRIDE + nf * 8 + gg]);
                mma_tf32(of[nf], a, bfr);
            }
        }
        __syncthreads();
    }

    float inv0 = 1.0f / l0;
    float inv1 = 1.0f / l1;
    __half* op = out + tokbase * DIM + h * DH;
#pragma unroll
    for (int nf = 0; nf < 8; nf++) {
        int c0 = nf * 8 + 2 * cc;
        __half2 w0 = __floats2half2_rn(of[nf][0] * inv0, of[nf][1] * inv0);
        __half2 w1 = __floats2half2_rn(of[nf][2] * inv1, of[nf][3] * inv1);
        *(__half2*)(op + (size_t)(wm + gg) * DIM + c0)     = w0;
        *(__half2*)(op + (size_t)(wm + gg + 8) * DIM + c0) = w1;
    }
}

// =====================================================================
// launch
// =====================================================================
extern "C" void kernel_launch(void* const* d_in, const int* in_sizes, int n_in,
                              void* d_out, int out_size)
{
    const float* x      = (const float*)d_in[0];
    const float* w_qkv  = (const float*)d_in[1];
    const float* w_out  = (const float*)d_in[2];
    const float* b_out  = (const float*)d_in[3];
    const float* w1     = (const float*)d_in[4];
    const float* b1     = (const float*)d_in[5];
    const float* w2     = (const float*)d_in[6];
    const float* b2     = (const float*)d_in[7];
    const float* gamma1 = (const float*)d_in[8];
    const float* beta1  = (const float*)d_in[9];
    const float* gamma2 = (const float*)d_in[10];
    const float* beta2  = (const float*)d_in[11];
    float* out = (float*)d_out;

    __half *xn, *att, *h, *ff;
    float *qkv, *x1;
    unsigned *wqkv, *wout, *w1p, *w2p;
    cudaGetSymbolAddress((void**)&xn,   g_xn);
    cudaGetSymbolAddress((void**)&qkv,  g_qkv);
    cudaGetSymbolAddress((void**)&att,  g_att);
    cudaGetSymbolAddress((void**)&x1,   g_x1);
    cudaGetSymbolAddress((void**)&h,    g_h);
    cudaGetSymbolAddress((void**)&ff,   g_ff);
    cudaGetSymbolAddress((void**)&wqkv, g_wqkv);
    cudaGetSymbolAddress((void**)&wout, g_wout);
    cudaGetSymbolAddress((void**)&w1p,  g_w1);
    cudaGetSymbolAddress((void**)&w2p,  g_w2);

    static bool attr_done = false;
    if (!attr_done) {
        cudaFuncSetAttribute(gemm_fp16_kernel<float, false, false, false, true>,
                             cudaFuncAttributeMaxDynamicSharedMemorySize, GEMM_SMEM_BYTES);
        cudaFuncSetAttribute(gemm_fp16_kernel<float, true, false, true, false>,
                             cudaFuncAttributeMaxDynamicSharedMemorySize, GEMM_SMEM_BYTES);
        cudaFuncSetAttribute(gemm_fp16_kernel<__half, true, true, false, false>,
                             cudaFuncAttributeMaxDynamicSharedMemorySize, GEMM_SMEM_BYTES);
        cudaFuncSetAttribute(attn_tc_kernel,
                             cudaFuncAttributeMaxDynamicSharedMemorySize, ATT_SMEM_BYTES);
        attr_done = true;
    }

    // 0) pack weights to fp16 k-paired layout
    pack_w_kernel<<<dim3(3 * DIM / 256, DIM / 2), 256>>>(w_qkv, wqkv, DIM, 3 * DIM);
    pack_w_kernel<<<dim3(DIM / 256, DIM / 2), 256>>>(w_out, wout, DIM, DIM);
    pack_w_kernel<<<dim3(HID / 256, DIM / 2), 256>>>(w1, w1p, DIM, HID);
    pack_w_kernel<<<dim3(DIM / 256, HID / 2), 256>>>(w2, w2p, HID, DIM);

    // 1) xn = fp16(LN1(x))
    ln_kernel<<<TOK, 256>>>(x, gamma1, beta1, xn);

    // 2) qkv = tf32(xn @ w_qkv)   (fp32 out, rounded for tf32 attention)
    gemm_fp16_kernel<float, false, false, false, true>
        <<<dim3(3 * DIM / 128, TOK / 128), 128, GEMM_SMEM_BYTES>>>(
        xn, wqkv, nullptr, nullptr, qkv, TOK, 3 * DIM, DIM);

    // 3) att = fp16(attention(qkv))
    attn_tc_kernel<<<dim3(SEQ / 128, BATCH * HEADS), 256, ATT_SMEM_BYTES>>>(qkv, att);

    // 4) x1 = x + att @ w_out + b_out    (fp32)
    gemm_fp16_kernel<float, true, false, true, false>
        <<<dim3(DIM / 128, TOK / 128), 128, GEMM_SMEM_BYTES>>>(
        att, wout, b_out, x, x1, TOK, DIM, DIM);

    // 5) h = fp16(LN2(x1))
    ln_kernel<<<TOK, 256>>>(x1, gamma2, beta2, h);

    // 6) ff = fp16(relu(h @ w1 + b1))
    gemm_fp16_kernel<__half, true, true, false, false>
        <<<dim3(HID / 128, TOK / 128), 128, GEMM_SMEM_BYTES>>>(
        h, w1p, b1, nullptr, ff, TOK, HID, DIM);

    // 7) out = x1 + ff @ w2 + b2   (fp32)
    gemm_fp16_kernel<float, true, false, true, false>
        <<<dim3(DIM / 128, TOK / 128), 128, GEMM_SMEM_BYTES>>>(
        ff, w2p, b2, x1, out, TOK, DIM, HID);
}

// round 7
// speedup vs baseline: 10.5139x; 1.0785x over previous
#include <cuda_runtime.h>
#include <cuda_fp16.h>
#include <math.h>
#include <stddef.h>
#include <stdint.h>

// ---------------- problem constants ----------------
#define BATCH   4
#define SEQ     2048
#define DIM     1024
#define HEADS   16
#define DH      64
#define HID     4096
#define TOK     (BATCH * SEQ)          // 8192
#define EPS     1e-5f
#define ATT_SCALE 0.03125f             // DIM^-0.5 = 1/32 (power of 2: exact)

// ---------------- scratch (no cudaMalloc allowed) ----------------
__device__ __half g_xn [TOK * DIM];
__device__ __half g_qkv[TOK * 3 * DIM];
__device__ __half g_att[TOK * DIM];
__device__ float  g_x1 [TOK * DIM];
__device__ __half g_h  [TOK * DIM];
__device__ __half g_ff [TOK * HID];
// packed fp16 weights: [K/2][N] of half2 (k-pairs)
__device__ unsigned g_wqkv[(DIM / 2) * 3 * DIM];
__device__ unsigned g_wout[(DIM / 2) * DIM];
__device__ unsigned g_w1  [(DIM / 2) * HID];
__device__ unsigned g_w2  [(HID / 2) * DIM];

// ---------------- helpers ----------------
__device__ __forceinline__ float to_tf32(float x) {
    unsigned u;
    asm("cvt.rna.tf32.f32 %0, %1;" : "=r"(u) : "f"(x));
    return __uint_as_float(u);
}
__device__ __forceinline__ void cp16(unsigned dst, const void* src) {
    asm volatile("cp.async.cg.shared.global [%0], [%1], 16;" :: "r"(dst), "l"(src));
}
__device__ __forceinline__ void cp_commit() {
    asm volatile("cp.async.commit_group;" ::: "memory");
}
__device__ __forceinline__ void cp_wait1() {
    asm volatile("cp.async.wait_group 1;" ::: "memory");
}
__device__ __forceinline__ void cp_wait0() {
    asm volatile("cp.async.wait_group 0;" ::: "memory");
}

// fp16 mma, fp32 accumulate: D(16x8) += A(16x16) B(16x8)
__device__ __forceinline__ void mma_fp16(
    float* c, const unsigned* a, const unsigned* b)
{
    asm volatile(
        "mma.sync.aligned.m16n8k16.row.col.f32.f16.f16.f32 "
        "{%0,%1,%2,%3}, {%4,%5,%6,%7}, {%8,%9}, {%0,%1,%2,%3};"
        : "+f"(c[0]), "+f"(c[1]), "+f"(c[2]), "+f"(c[3])
        : "r"(a[0]), "r"(a[1]), "r"(a[2]), "r"(a[3]), "r"(b[0]), "r"(b[1]));
}

// =====================================================================
// weight pack: out[k2][n] = half2(w[2k2][n], w[2k2+1][n])
// =====================================================================
__global__ void __launch_bounds__(256) pack_w_kernel(
    const float* __restrict__ w, unsigned* __restrict__ out, int K, int N)
{
    int n = blockIdx.x * 256 + threadIdx.x;
    int k2 = blockIdx.y;
    float lo = w[(size_t)(2 * k2) * N + n];
    float hi = w[(size_t)(2 * k2 + 1) * N + n];
    __half2 h = __floats2half2_rn(lo, hi);
    out[(size_t)k2 * N + n] = *(unsigned*)&h;
}

// =====================================================================
// LayerNorm (torch semantics), fp16 output.
// =====================================================================
__global__ void __launch_bounds__(256) ln_kernel(
    const float* __restrict__ x, const float* __restrict__ gamma,
    const float* __restrict__ beta, __half* __restrict__ y)
{
    int row = blockIdx.x;
    int t = threadIdx.x;
    const float* xr = x + (size_t)row * DIM;
    float4 v = *(const float4*)(xr + t * 4);

    __shared__ float red[8];

    float s = v.x + v.y + v.z + v.w;
#pragma unroll
    for (int o = 16; o > 0; o >>= 1) s += __shfl_xor_sync(0xffffffffu, s, o);
    if ((t & 31) == 0) red[t >> 5] = s;
    __syncthreads();
    float tot = 0.f;
#pragma unroll
    for (int i = 0; i < 8; i++) tot += red[i];
    float mean = tot * (1.0f / DIM);

    float dx = v.x - mean, dy = v.y - mean, dz = v.z - mean, dw = v.w - mean;
    float ss = dx * dx + dy * dy + dz * dz + dw * dw;
#pragma unroll
    for (int o = 16; o > 0; o >>= 1) ss += __shfl_xor_sync(0xffffffffu, ss, o);
    __syncthreads();
    if ((t & 31) == 0) red[t >> 5] = ss;
    __syncthreads();
    float tss = 0.f;
#pragma unroll
    for (int i = 0; i < 8; i++) tss += red[i];

    float inv = 1.0f / (sqrtf(tss * (1.0f / (DIM - 1))) + EPS);

    float4 gv = *(const float4*)(gamma + t * 4);
    float4 bv = *(const float4*)(beta + t * 4);
    __half2 h01 = __floats2half2_rn(gv.x * dx * inv + bv.x, gv.y * dy * inv + bv.y);
    __half2 h23 = __floats2half2_rn(gv.z * dz * inv + bv.z, gv.w * dw * inv + bv.w);
    __half2* yp = (__half2*)(y + (size_t)row * DIM + t * 4);
    yp[0] = h01;
    yp[1] = h23;
}

// =====================================================================
// fp16 tensor-core GEMM (unchanged structure from R6)
// =====================================================================
#define AH_STRIDE 72
#define A_BUF_BYTES (128 * AH_STRIDE * 2)
#define BW_STRIDE 136
#define B_BUF_BYTES (32 * BW_STRIDE * 4)
#define GEMM_SMEM_BYTES (2 * A_BUF_BYTES + 2 * B_BUF_BYTES)   // 71680

template <typename OutT, bool BIAS, bool RELU, bool RES>
__global__ void __launch_bounds__(128, 2) gemm_fp16_kernel(
    const __half* __restrict__ A, const unsigned* __restrict__ Bp,
    const float* __restrict__ bias, const float* __restrict__ res,
    OutT* __restrict__ C, int M, int N, int K)
{
    extern __shared__ char smraw[];
    unsigned sbase = (unsigned)__cvta_generic_to_shared(smraw);
    const __half* As_all = (const __half*)smraw;
    const unsigned* Bs_all = (const unsigned*)(smraw + 2 * A_BUF_BYTES);

    int tid = threadIdx.x;
    int warp = tid >> 5;
    int lane = tid & 31;
    int bm = blockIdx.y * 128;
    int bn = blockIdx.x * 128;
    int wm = (warp & 1) * 64;
    int wn = (warp >> 1) * 64;
    int gg = lane >> 2;
    int cc = lane & 3;

    float acc[4][8][4];
#pragma unroll
    for (int f = 0; f < 4; f++)
#pragma unroll
        for (int nf = 0; nf < 8; nf++)
#pragma unroll
            for (int q = 0; q < 4; q++) acc[f][nf][q] = 0.f;

    auto load_tiles = [&](int t, int s) {
        int k0 = t * 64;
        unsigned abase = sbase + s * A_BUF_BYTES;
        unsigned bbase = sbase + 2 * A_BUF_BYTES + s * B_BUF_BYTES;
#pragma unroll
        for (int j = 0; j < 8; j++) {
            int idx = tid + j * 128;
            int r = idx >> 3, c = idx & 7;
            cp16(abase + r * (AH_STRIDE * 2) + c * 16,
                 A + (size_t)(bm + r) * K + k0 + c * 8);
        }
#pragma unroll
        for (int j = 0; j < 8; j++) {
            int idx = tid + j * 128;
            int r = idx >> 5, c4 = idx & 31;
            cp16(bbase + r * (BW_STRIDE * 4) + c4 * 16,
                 Bp + (size_t)(t * 32 + r) * N + bn + c4 * 4);
        }
        cp_commit();
    };

    int nT = K >> 6;
    load_tiles(0, 0);

    for (int t = 0; t < nT; t++) {
        if (t + 1 < nT) {
            load_tiles(t + 1, (t + 1) & 1);
            cp_wait1();
        } else {
            cp_wait0();
        }
        __syncthreads();

        const __half* as = (const __half*)((const char*)As_all + (t & 1) * A_BUF_BYTES);
        const unsigned* bs = (const unsigned*)((const char*)Bs_all + (t & 1) * B_BUF_BYTES);

#pragma unroll
        for (int ks = 0; ks < 4; ks++) {
            int kb = ks * 16;
            unsigned a[4][4], b[8][2];
#pragma unroll
            for (int f = 0; f < 4; f++) {
                int r = wm + f * 16 + gg;
                a[f][0] = *(const unsigned*)&as[r * AH_STRIDE + kb + 2 * cc];
                a[f][1] = *(const unsigned*)&as[(r + 8) * AH_STRIDE + kb + 2 * cc];
                a[f][2] = *(const unsigned*)&as[r * AH_STRIDE + kb + 2 * cc + 8];
                a[f][3] = *(const unsigned*)&as[(r + 8) * AH_STRIDE + kb + 2 * cc + 8];
            }
#pragma unroll
            for (int nf = 0; nf < 8; nf++) {
                int col = wn + nf * 8 + gg;
                b[nf][0] = bs[(kb / 2 + cc) * BW_STRIDE + col];
                b[nf][1] = bs[(kb / 2 + cc + 4) * BW_STRIDE + col];
            }
#pragma unroll
            for (int f = 0; f < 4; f++)
#pragma unroll
                for (int nf = 0; nf < 8; nf++)
                    mma_fp16(acc[f][nf], a[f], b[nf]);
        }
        __syncthreads();
    }

#pragma unroll
    for (int f = 0; f < 4; f++) {
#pragma unroll
        for (int nf = 0; nf < 8; nf++) {
            int col = bn + wn + nf * 8 + 2 * cc;
#pragma unroll
            for (int half_i = 0; half_i < 2; half_i++) {
                int row = bm + wm + f * 16 + gg + half_i * 8;
                float v0 = acc[f][nf][half_i * 2 + 0];
                float v1 = acc[f][nf][half_i * 2 + 1];
                if (BIAS) { v0 += bias[col]; v1 += bias[col + 1]; }
                if (RES) {
                    const float* rp = res + (size_t)row * N + col;
                    v0 += rp[0]; v1 += rp[1];
                }
                if (RELU) { v0 = fmaxf(v0, 0.f); v1 = fmaxf(v1, 0.f); }
                if (sizeof(OutT) == 2) {
                    __half2 hv = __floats2half2_rn(v0, v1);
                    *(__half2*)((__half*)C + (size_t)row * N + col) = hv;
                } else {
                    float2 w; w.x = v0; w.y = v1;
                    *(float2*)((float*)C + (size_t)row * N + col) = w;
                }
            }
        }
    }
}

// =====================================================================
// fp16 tensor-core flash attention.
// grid (SEQ/128, BATCH*HEADS), 256 threads = 8 warps, 16 q-rows/warp.
// K tiles: cp.async, 128B-XOR-swizzled (conflict-free b-frags).
// V tiles: transposed key-paired half2 [dh][key/2], stride 36 words.
// P: half2 pairs [row][key/2], stride 36 words.
// smem 53248 B -> 2 CTA/SM.
// =====================================================================
#define KSW_BYTES 8192                        // 64 rows x 128B, per buffer
#define VT_STRIDE 36                          // words
#define VT_BYTES  (64 * VT_STRIDE * 4)        // 9216 per buffer
#define P2_STRIDE 36                          // words
#define P2_BYTES  (128 * P2_STRIDE * 4)       // 18432
#define ATTF_SMEM (2 * KSW_BYTES + 2 * VT_BYTES + P2_BYTES)   // 53248

__global__ void __launch_bounds__(256) attn_fp16_kernel(
    const __half* __restrict__ qkv, __half* __restrict__ out)
{
    extern __shared__ char sm[];
    unsigned sbase = (unsigned)__cvta_generic_to_shared(sm);
    char* ksm = sm;
    unsigned* vtsm = (unsigned*)(sm + 2 * KSW_BYTES);
    unsigned* p2sm = (unsigned*)(sm + 2 * KSW_BYTES + 2 * VT_BYTES);

    int tid = threadIdx.x;
    int warp = tid >> 5;
    int lane = tid & 31;
    int gg = lane >> 2;
    int cc = lane & 3;
    int wm = warp * 16;

    int bh = blockIdx.y;
    int b = bh >> 4;
    int h = bh & 15;
    size_t tokbase = (size_t)b * SEQ + blockIdx.x * 128;
    const __half* qb = qkv + tokbase * (3 * DIM) + h * DH;

    // ---- loader for tile kt into stage s ----
    auto load_kv = [&](int kt, int s) {
        const __half* kb = qkv + ((size_t)b * SEQ + kt) * (3 * DIM) + DIM + h * DH;
        const __half* vb = kb + DIM;
        // K: 64 rows x 128B via cp.async, XOR swizzle
        unsigned kdst = sbase + s * KSW_BYTES;
#pragma unroll
        for (int j = 0; j < 2; j++) {
            int idx = tid + j * 256;           // 512 chunks
            int r = idx >> 3, c = idx & 7;
            unsigned off = r * 128 + c * 16;
            cp16(kdst + (off ^ ((unsigned)(r & 7) << 4)),
                 kb + (size_t)r * (3 * DIM) + c * 8);
        }
        cp_commit();
        // V transpose: VT[dh][pair] = half2(V[2p][dh], V[2p+1][dh])
        unsigned* vt = vtsm + s * (VT_BYTES / 4);
#pragma unroll
        for (int j = 0; j < 4; j++) {
            int idx2 = tid + j * 256;          // 1024: dh-pair x key-pair
            int dh2 = idx2 & 31;               // dh pair index
            int p = idx2 >> 5;                 // key pair 0..31
            __half2 va = *(const __half2*)(vb + (size_t)(2 * p) * (3 * DIM) + 2 * dh2);
            __half2 vc = *(const __half2*)(vb + (size_t)(2 * p + 1) * (3 * DIM) + 2 * dh2);
            __half2 e0 = __halves2half2(__low2half(va), __low2half(vc));
            __half2 e1 = __halves2half2(__high2half(va), __high2half(vc));
            vt[(2 * dh2) * VT_STRIDE + p] = *(unsigned*)&e0;
            vt[(2 * dh2 + 1) * VT_STRIDE + p] = *(unsigned*)&e1;
        }
    };

    load_kv(0, 0);

    // ---- preload Q fragments (scaled by 1/32, exact in fp16) ----
    unsigned qf[4][4];
    {
        __half2 sc = __float2half2_rn(ATT_SCALE);
        const __half* r0 = qb + (size_t)(wm + gg) * (3 * DIM);
        const __half* r1 = qb + (size_t)(wm + gg + 8) * (3 * DIM);
#pragma unroll
        for (int kf = 0; kf < 4; kf++) {
            int c0 = kf * 16 + 2 * cc;
            __half2 v;
            v = __hmul2(*(const __half2*)(r0 + c0), sc);      qf[kf][0] = *(unsigned*)&v;
            v = __hmul2(*(const __half2*)(r1 + c0), sc);      qf[kf][1] = *(unsigned*)&v;
            v = __hmul2(*(const __half2*)(r0 + c0 + 8), sc);  qf[kf][2] = *(unsigned*)&v;
            v = __hmul2(*(const __half2*)(r1 + c0 + 8), sc);  qf[kf][3] = *(unsigned*)&v;
        }
    }

    float of[8][4];
#pragma unroll
    for (int nf = 0; nf < 8; nf++)
#pragma unroll
        for (int q = 0; q < 4; q++) of[nf][q] = 0.f;
    float m0 = -1e30f, m1 = -1e30f, l0 = 0.f, l1 = 0.f;

    for (int t = 0; t < SEQ / 64; t++) {
        if (t + 1 < SEQ / 64) { load_kv((t + 1) * 64, (t + 1) & 1); cp_wait1(); }
        else cp_wait0();
        __syncthreads();

        const char* K = ksm + (t & 1) * KSW_BYTES;
        const unsigned* V = vtsm + (t & 1) * (VT_BYTES / 4);

        // ---- S = Q K^T (fp16 mma, fp32 acc) ----
        float s[8][4];
#pragma unroll
        for (int nf = 0; nf < 8; nf++) {
#pragma unroll
            for (int q = 0; q < 4; q++) s[nf][q] = 0.f;
            int r = nf * 8 + gg;
            unsigned sw = (unsigned)(r & 7) << 4;
#pragma unroll
            for (int kf = 0; kf < 4; kf++) {
                unsigned off0 = r * 128 + (kf * 16 + 2 * cc) * 2;
                unsigned bfr[2];
                bfr[0] = *(const unsigned*)(K + (off0 ^ sw));
                bfr[1] = *(const unsigned*)(K + ((off0 + 16) ^ sw));
                mma_fp16(s[nf], qf[kf], bfr);
            }
        }

        // ---- online softmax ----
        float rmax0 = -1e30f, rmax1 = -1e30f;
#pragma unroll
        for (int nf = 0; nf < 8; nf++) {
            rmax0 = fmaxf(rmax0, fmaxf(s[nf][0], s[nf][1]));
            rmax1 = fmaxf(rmax1, fmaxf(s[nf][2], s[nf][3]));
        }
        rmax0 = fmaxf(rmax0, __shfl_xor_sync(0xffffffffu, rmax0, 1));
        rmax0 = fmaxf(rmax0, __shfl_xor_sync(0xffffffffu, rmax0, 2));
        rmax1 = fmaxf(rmax1, __shfl_xor_sync(0xffffffffu, rmax1, 1));
        rmax1 = fmaxf(rmax1, __shfl_xor_sync(0xffffffffu, rmax1, 2));

        float mn0 = fmaxf(m0, rmax0);
        float mn1 = fmaxf(m1, rmax1);
        float f0 = __expf(m0 - mn0);
        float f1 = __expf(m1 - mn1);
        m0 = mn0; m1 = mn1;

        float rs0 = 0.f, rs1 = 0.f;
#pragma unroll
        for (int nf = 0; nf < 8; nf++) {
            float p0 = __expf(s[nf][0] - mn0);
            float p1 = __expf(s[nf][1] - mn0);
            float p2 = __expf(s[nf][2] - mn1);
            float p3 = __expf(s[nf][3] - mn1);
            rs0 += p0 + p1;
            rs1 += p2 + p3;
            __half2 hp0 = __floats2half2_rn(p0, p1);
            __half2 hp1 = __floats2half2_rn(p2, p3);
            p2sm[(wm + gg) * P2_STRIDE + nf * 4 + cc] = *(unsigned*)&hp0;
            p2sm[(wm + gg + 8) * P2_STRIDE + nf * 4 + cc] = *(unsigned*)&hp1;
        }
        rs0 += __shfl_xor_sync(0xffffffffu, rs0, 1);
        rs0 += __shfl_xor_sync(0xffffffffu, rs0, 2);
        rs1 += __shfl_xor_sync(0xffffffffu, rs1, 1);
        rs1 += __shfl_xor_sync(0xffffffffu, rs1, 2);
        l0 = l0 * f0 + rs0;
        l1 = l1 * f1 + rs1;

#pragma unroll
        for (int nf = 0; nf < 8; nf++) {
            of[nf][0] *= f0; of[nf][1] *= f0;
            of[nf][2] *= f1; of[nf][3] *= f1;
        }
        __syncwarp();

        // ---- O += P V ----
#pragma unroll
        for (int kf = 0; kf < 4; kf++) {
            unsigned a[4];
            a[0] = p2sm[(wm + gg) * P2_STRIDE + kf * 8 + cc];
            a[1] = p2sm[(wm + gg + 8) * P2_STRIDE + kf * 8 + cc];
            a[2] = p2sm[(wm + gg) * P2_STRIDE + kf * 8 + cc + 4];
            a[3] = p2sm[(wm + gg + 8) * P2_STRIDE + kf * 8 + cc + 4];
#pragma unroll
            for (int nf = 0; nf < 8; nf++) {
                unsigned bfr[2];
                bfr[0] = V[(nf * 8 + gg) * VT_STRIDE + kf * 8 + cc];
                bfr[1] = V[(nf * 8 + gg) * VT_STRIDE + kf * 8 + cc + 4];
                mma_fp16(of[nf], a, bfr);
            }
        }
        __syncthreads();
    }

    // ---- epilogue ----
    float inv0 = 1.0f / l0;
    float inv1 = 1.0f / l1;
    __half* op = out + tokbase * DIM + h * DH;
#pragma unroll
    for (int nf = 0; nf < 8; nf++) {
        int c0 = nf * 8 + 2 * cc;
        __half2 w0 = __floats2half2_rn(of[nf][0] * inv0, of[nf][1] * inv0);
        __half2 w1 = __floats2half2_rn(of[nf][2] * inv1, of[nf][3] * inv1);
        *(__half2*)(op + (size_t)(wm + gg) * DIM + c0)     = w0;
        *(__half2*)(op + (size_t)(wm + gg + 8) * DIM + c0) = w1;
    }
}

// =====================================================================
// launch
// =====================================================================
extern "C" void kernel_launch(void* const* d_in, const int* in_sizes, int n_in,
                              void* d_out, int out_size)
{
    const float* x      = (const float*)d_in[0];
    const float* w_qkv  = (const float*)d_in[1];
    const float* w_out  = (const float*)d_in[2];
    const float* b_out  = (const float*)d_in[3];
    const float* w1     = (const float*)d_in[4];
    const float* b1     = (const float*)d_in[5];
    const float* w2     = (const float*)d_in[6];
    const float* b2     = (const float*)d_in[7];
    const float* gamma1 = (const float*)d_in[8];
    const float* beta1  = (const float*)d_in[9];
    const float* gamma2 = (const float*)d_in[10];
    const float* beta2  = (const float*)d_in[11];
    float* out = (float*)d_out;

    __half *xn, *qkv, *att, *h, *ff;
    float *x1;
    unsigned *wqkv, *wout, *w1p, *w2p;
    cudaGetSymbolAddress((void**)&xn,   g_xn);
    cudaGetSymbolAddress((void**)&qkv,  g_qkv);
    cudaGetSymbolAddress((void**)&att,  g_att);
    cudaGetSymbolAddress((void**)&x1,   g_x1);
    cudaGetSymbolAddress((void**)&h,    g_h);
    cudaGetSymbolAddress((void**)&ff,   g_ff);
    cudaGetSymbolAddress((void**)&wqkv, g_wqkv);
    cudaGetSymbolAddress((void**)&wout, g_wout);
    cudaGetSymbolAddress((void**)&w1p,  g_w1);
    cudaGetSymbolAddress((void**)&w2p,  g_w2);

    static bool attr_done = false;
    if (!attr_done) {
        cudaFuncSetAttribute(gemm_fp16_kernel<__half, false, false, false>,
                             cudaFuncAttributeMaxDynamicSharedMemorySize, GEMM_SMEM_BYTES);
        cudaFuncSetAttribute(gemm_fp16_kernel<float, true, false, true>,
                             cudaFuncAttributeMaxDynamicSharedMemorySize, GEMM_SMEM_BYTES);
        cudaFuncSetAttribute(gemm_fp16_kernel<__half, true, true, false>,
                             cudaFuncAttributeMaxDynamicSharedMemorySize, GEMM_SMEM_BYTES);
        cudaFuncSetAttribute(attn_fp16_kernel,
                             cudaFuncAttributeMaxDynamicSharedMemorySize, ATTF_SMEM);
        attr_done = true;
    }

    // 0) pack weights to fp16 k-paired layout
    pack_w_kernel<<<dim3(3 * DIM / 256, DIM / 2), 256>>>(w_qkv, wqkv, DIM, 3 * DIM);
    pack_w_kernel<<<dim3(DIM / 256, DIM / 2), 256>>>(w_out, wout, DIM, DIM);
    pack_w_kernel<<<dim3(HID / 256, DIM / 2), 256>>>(w1, w1p, DIM, HID);
    pack_w_kernel<<<dim3(DIM / 256, HID / 2), 256>>>(w2, w2p, HID, DIM);

    // 1) xn = fp16(LN1(x))
    ln_kernel<<<TOK, 256>>>(x, gamma1, beta1, xn);

    // 2) qkv = fp16(xn @ w_qkv)
    gemm_fp16_kernel<__half, false, false, false>
        <<<dim3(3 * DIM / 128, TOK / 128), 128, GEMM_SMEM_BYTES>>>(
        xn, wqkv, nullptr, nullptr, qkv, TOK, 3 * DIM, DIM);

    // 3) att = fp16(attention(qkv))   — full fp16 tensor-core flash attention
    attn_fp16_kernel<<<dim3(SEQ / 128, BATCH * HEADS), 256, ATTF_SMEM>>>(qkv, att);

    // 4) x1 = x + att @ w_out + b_out    (fp32)
    gemm_fp16_kernel<float, true, false, true>
        <<<dim3(DIM / 128, TOK / 128), 128, GEMM_SMEM_BYTES>>>(
        att, wout, b_out, x, x1, TOK, DIM, DIM);

    // 5) h = fp16(LN2(x1))
    ln_kernel<<<TOK, 256>>>(x1, gamma2, beta2, h);

    // 6) ff = fp16(relu(h @ w1 + b1))
    gemm_fp16_kernel<__half, true, true, false>
        <<<dim3(HID / 128, TOK / 128), 128, GEMM_SMEM_BYTES>>>(
        h, w1p, b1, nullptr, ff, TOK, HID, DIM);

    // 7) out = x1 + ff @ w2 + b2   (fp32)
    gemm_fp16_kernel<float, true, false, true>
        <<<dim3(DIM / 128, TOK / 128), 128, GEMM_SMEM_BYTES>>>(
        ff, w2p, b2, x1, out, TOK, DIM, HID);
}

// round 8
// speedup vs baseline: 11.9122x; 1.1330x over previous
#include <cuda_runtime.h>
#include <cuda_fp16.h>
#include <math.h>
#include <stddef.h>
#include <stdint.h>

// ---------------- problem constants ----------------
#define BATCH   4
#define SEQ     2048
#define DIM     1024
#define HEADS   16
#define DH      64
#define HID     4096
#define TOK     (BATCH * SEQ)          // 8192
#define EPS     1e-5f
#define ATT_SCALE 0.03125f             // DIM^-0.5 = 1/32
#define LOG2E   1.44269504088896f

// ---------------- scratch (no cudaMalloc allowed) ----------------
__device__ __half g_xn [TOK * DIM];
__device__ __half g_qkv[TOK * 3 * DIM];
__device__ __half g_att[TOK * DIM];
__device__ float  g_x1 [TOK * DIM];
__device__ __half g_h  [TOK * DIM];
__device__ __half g_ff [TOK * HID];
// packed fp16 weights: [K/2][N] of half2 (k-pairs)
__device__ unsigned g_wqkv[(DIM / 2) * 3 * DIM];
__device__ unsigned g_wout[(DIM / 2) * DIM];
__device__ unsigned g_w1  [(DIM / 2) * HID];
__device__ unsigned g_w2  [(HID / 2) * DIM];

// ---------------- helpers ----------------
__device__ __forceinline__ void cp16(unsigned dst, const void* src) {
    asm volatile("cp.async.cg.shared.global [%0], [%1], 16;" :: "r"(dst), "l"(src));
}
__device__ __forceinline__ void cp_commit() {
    asm volatile("cp.async.commit_group;" ::: "memory");
}
__device__ __forceinline__ void cp_wait1() {
    asm volatile("cp.async.wait_group 1;" ::: "memory");
}
__device__ __forceinline__ void cp_wait0() {
    asm volatile("cp.async.wait_group 0;" ::: "memory");
}

// fp16 mma, fp32 accumulate: D(16x8) += A(16x16) B(16x8)
__device__ __forceinline__ void mma_fp16(
    float* c, const unsigned* a, const unsigned* b)
{
    asm volatile(
        "mma.sync.aligned.m16n8k16.row.col.f32.f16.f16.f32 "
        "{%0,%1,%2,%3}, {%4,%5,%6,%7}, {%8,%9}, {%0,%1,%2,%3};"
        : "+f"(c[0]), "+f"(c[1]), "+f"(c[2]), "+f"(c[3])
        : "r"(a[0]), "r"(a[1]), "r"(a[2]), "r"(a[3]), "r"(b[0]), "r"(b[1]));
}

// dual fp16 exp2: out.lo = 2^in.lo, out.hi = 2^in.hi (one MUFU op)
__device__ __forceinline__ unsigned ex2_f16x2(unsigned in) {
    unsigned out;
    asm("ex2.approx.f16x2 %0, %1;" : "=r"(out) : "r"(in));
    return out;
}

// =====================================================================
// weight pack: out[k2][n] = half2(w[2k2][n], w[2k2+1][n])
// =====================================================================
__global__ void __launch_bounds__(256) pack_w_kernel(
    const float* __restrict__ w, unsigned* __restrict__ out, int K, int N)
{
    int n = blockIdx.x * 256 + threadIdx.x;
    int k2 = blockIdx.y;
    float lo = w[(size_t)(2 * k2) * N + n];
    float hi = w[(size_t)(2 * k2 + 1) * N + n];
    __half2 h = __floats2half2_rn(lo, hi);
    out[(size_t)k2 * N + n] = *(unsigned*)&h;
}

// =====================================================================
// LayerNorm (torch semantics), fp16 output.
// =====================================================================
__global__ void __launch_bounds__(256) ln_kernel(
    const float* __restrict__ x, const float* __restrict__ gamma,
    const float* __restrict__ beta, __half* __restrict__ y)
{
    int row = blockIdx.x;
    int t = threadIdx.x;
    const float* xr = x + (size_t)row * DIM;
    float4 v = *(const float4*)(xr + t * 4);

    __shared__ float red[8];

    float s = v.x + v.y + v.z + v.w;
#pragma unroll
    for (int o = 16; o > 0; o >>= 1) s += __shfl_xor_sync(0xffffffffu, s, o);
    if ((t & 31) == 0) red[t >> 5] = s;
    __syncthreads();
    float tot = 0.f;
#pragma unroll
    for (int i = 0; i < 8; i++) tot += red[i];
    float mean = tot * (1.0f / DIM);

    float dx = v.x - mean, dy = v.y - mean, dz = v.z - mean, dw = v.w - mean;
    float ss = dx * dx + dy * dy + dz * dz + dw * dw;
#pragma unroll
    for (int o = 16; o > 0; o >>= 1) ss += __shfl_xor_sync(0xffffffffu, ss, o);
    __syncthreads();
    if ((t & 31) == 0) red[t >> 5] = ss;
    __syncthreads();
    float tss = 0.f;
#pragma unroll
    for (int i = 0; i < 8; i++) tss += red[i];

    float inv = 1.0f / (sqrtf(tss * (1.0f / (DIM - 1))) + EPS);

    float4 gv = *(const float4*)(gamma + t * 4);
    float4 bv = *(const float4*)(beta + t * 4);
    __half2 h01 = __floats2half2_rn(gv.x * dx * inv + bv.x, gv.y * dy * inv + bv.y);
    __half2 h23 = __floats2half2_rn(gv.z * dz * inv + bv.z, gv.w * dw * inv + bv.w);
    __half2* yp = (__half2*)(y + (size_t)row * DIM + t * 4);
    yp[0] = h01;
    yp[1] = h23;
}

// =====================================================================
// fp16 tensor-core GEMM (unchanged from R7)
// =====================================================================
#define AH_STRIDE 72
#define A_BUF_BYTES (128 * AH_STRIDE * 2)
#define BW_STRIDE 136
#define B_BUF_BYTES (32 * BW_STRIDE * 4)
#define GEMM_SMEM_BYTES (2 * A_BUF_BYTES + 2 * B_BUF_BYTES)   // 71680

template <typename OutT, bool BIAS, bool RELU, bool RES>
__global__ void __launch_bounds__(128, 2) gemm_fp16_kernel(
    const __half* __restrict__ A, const unsigned* __restrict__ Bp,
    const float* __restrict__ bias, const float* __restrict__ res,
    OutT* __restrict__ C, int M, int N, int K)
{
    extern __shared__ char smraw[];
    unsigned sbase = (unsigned)__cvta_generic_to_shared(smraw);
    const __half* As_all = (const __half*)smraw;
    const unsigned* Bs_all = (const unsigned*)(smraw + 2 * A_BUF_BYTES);

    int tid = threadIdx.x;
    int warp = tid >> 5;
    int lane = tid & 31;
    int bm = blockIdx.y * 128;
    int bn = blockIdx.x * 128;
    int wm = (warp & 1) * 64;
    int wn = (warp >> 1) * 64;
    int gg = lane >> 2;
    int cc = lane & 3;

    float acc[4][8][4];
#pragma unroll
    for (int f = 0; f < 4; f++)
#pragma unroll
        for (int nf = 0; nf < 8; nf++)
#pragma unroll
            for (int q = 0; q < 4; q++) acc[f][nf][q] = 0.f;

    auto load_tiles = [&](int t, int s) {
        int k0 = t * 64;
        unsigned abase = sbase + s * A_BUF_BYTES;
        unsigned bbase = sbase + 2 * A_BUF_BYTES + s * B_BUF_BYTES;
#pragma unroll
        for (int j = 0; j < 8; j++) {
            int idx = tid + j * 128;
            int r = idx >> 3, c = idx & 7;
            cp16(abase + r * (AH_STRIDE * 2) + c * 16,
                 A + (size_t)(bm + r) * K + k0 + c * 8);
        }
#pragma unroll
        for (int j = 0; j < 8; j++) {
            int idx = tid + j * 128;
            int r = idx >> 5, c4 = idx & 31;
            cp16(bbase + r * (BW_STRIDE * 4) + c4 * 16,
                 Bp + (size_t)(t * 32 + r) * N + bn + c4 * 4);
        }
        cp_commit();
    };

    int nT = K >> 6;
    load_tiles(0, 0);

    for (int t = 0; t < nT; t++) {
        if (t + 1 < nT) {
            load_tiles(t + 1, (t + 1) & 1);
            cp_wait1();
        } else {
            cp_wait0();
        }
        __syncthreads();

        const __half* as = (const __half*)((const char*)As_all + (t & 1) * A_BUF_BYTES);
        const unsigned* bs = (const unsigned*)((const char*)Bs_all + (t & 1) * B_BUF_BYTES);

#pragma unroll
        for (int ks = 0; ks < 4; ks++) {
            int kb = ks * 16;
            unsigned a[4][4], b[8][2];
#pragma unroll
            for (int f = 0; f < 4; f++) {
                int r = wm + f * 16 + gg;
                a[f][0] = *(const unsigned*)&as[r * AH_STRIDE + kb + 2 * cc];
                a[f][1] = *(const unsigned*)&as[(r + 8) * AH_STRIDE + kb + 2 * cc];
                a[f][2] = *(const unsigned*)&as[r * AH_STRIDE + kb + 2 * cc + 8];
                a[f][3] = *(const unsigned*)&as[(r + 8) * AH_STRIDE + kb + 2 * cc + 8];
            }
#pragma unroll
            for (int nf = 0; nf < 8; nf++) {
                int col = wn + nf * 8 + gg;
                b[nf][0] = bs[(kb / 2 + cc) * BW_STRIDE + col];
                b[nf][1] = bs[(kb / 2 + cc + 4) * BW_STRIDE + col];
            }
#pragma unroll
            for (int f = 0; f < 4; f++)
#pragma unroll
                for (int nf = 0; nf < 8; nf++)
                    mma_fp16(acc[f][nf], a[f], b[nf]);
        }
        __syncthreads();
    }

#pragma unroll
    for (int f = 0; f < 4; f++) {
#pragma unroll
        for (int nf = 0; nf < 8; nf++) {
            int col = bn + wn + nf * 8 + 2 * cc;
#pragma unroll
            for (int half_i = 0; half_i < 2; half_i++) {
                int row = bm + wm + f * 16 + gg + half_i * 8;
                float v0 = acc[f][nf][half_i * 2 + 0];
                float v1 = acc[f][nf][half_i * 2 + 1];
                if (BIAS) { v0 += bias[col]; v1 += bias[col + 1]; }
                if (RES) {
                    const float* rp = res + (size_t)row * N + col;
                    v0 += rp[0]; v1 += rp[1];
                }
                if (RELU) { v0 = fmaxf(v0, 0.f); v1 = fmaxf(v1, 0.f); }
                if (sizeof(OutT) == 2) {
                    __half2 hv = __floats2half2_rn(v0, v1);
                    *(__half2*)((__half*)C + (size_t)row * N + col) = hv;
                } else {
                    float2 w; w.x = v0; w.y = v1;
                    *(float2*)((float*)C + (size_t)row * N + col) = w;
                }
            }
        }
    }
}

// =====================================================================
// fp16 flash attention, log2-domain softmax with ex2.approx.f16x2.
// grid (SEQ/128, BATCH*HEADS), 256 threads = 8 warps, 16 q-rows/warp.
// =====================================================================
#define KSW_BYTES 8192
#define VT_STRIDE 36
#define VT_BYTES  (64 * VT_STRIDE * 4)
#define P2_STRIDE 36
#define P2_BYTES  (128 * P2_STRIDE * 4)
#define ATTF_SMEM (2 * KSW_BYTES + 2 * VT_BYTES + P2_BYTES)   // 53248

__global__ void __launch_bounds__(256) attn_fp16_kernel(
    const __half* __restrict__ qkv, __half* __restrict__ out)
{
    extern __shared__ char sm[];
    unsigned sbase = (unsigned)__cvta_generic_to_shared(sm);
    char* ksm = sm;
    unsigned* vtsm = (unsigned*)(sm + 2 * KSW_BYTES);
    unsigned* p2sm = (unsigned*)(sm + 2 * KSW_BYTES + 2 * VT_BYTES);

    int tid = threadIdx.x;
    int warp = tid >> 5;
    int lane = tid & 31;
    int gg = lane >> 2;
    int cc = lane & 3;
    int wm = warp * 16;

    int bh = blockIdx.y;
    int b = bh >> 4;
    int h = bh & 15;
    size_t tokbase = (size_t)b * SEQ + blockIdx.x * 128;
    const __half* qb = qkv + tokbase * (3 * DIM) + h * DH;

    auto load_kv = [&](int kt, int s) {
        const __half* kb = qkv + ((size_t)b * SEQ + kt) * (3 * DIM) + DIM + h * DH;
        const __half* vb = kb + DIM;
        unsigned kdst = sbase + s * KSW_BYTES;
#pragma unroll
        for (int j = 0; j < 2; j++) {
            int idx = tid + j * 256;
            int r = idx >> 3, c = idx & 7;
            unsigned off = r * 128 + c * 16;
            cp16(kdst + (off ^ ((unsigned)(r & 7) << 4)),
                 kb + (size_t)r * (3 * DIM) + c * 8);
        }
        cp_commit();
        unsigned* vt = vtsm + s * (VT_BYTES / 4);
#pragma unroll
        for (int j = 0; j < 4; j++) {
            int idx2 = tid + j * 256;
            int dh2 = idx2 & 31;
            int p = idx2 >> 5;
            __half2 va = *(const __half2*)(vb + (size_t)(2 * p) * (3 * DIM) + 2 * dh2);
            __half2 vc = *(const __half2*)(vb + (size_t)(2 * p + 1) * (3 * DIM) + 2 * dh2);
            __half2 e0 = __halves2half2(__low2half(va), __low2half(vc));
            __half2 e1 = __halves2half2(__high2half(va), __high2half(vc));
            vt[(2 * dh2) * VT_STRIDE + p] = *(unsigned*)&e0;
            vt[(2 * dh2 + 1) * VT_STRIDE + p] = *(unsigned*)&e1;
        }
    };

    load_kv(0, 0);

    // ---- preload Q fragments scaled by ATT_SCALE*log2e (log2-domain S) ----
    unsigned qf[4][4];
    {
        const float SC = ATT_SCALE * LOG2E;
        const __half* r0 = qb + (size_t)(wm + gg) * (3 * DIM);
        const __half* r1 = qb + (size_t)(wm + gg + 8) * (3 * DIM);
#pragma unroll
        for (int kf = 0; kf < 4; kf++) {
            int c0 = kf * 16 + 2 * cc;
#pragma unroll
            for (int q = 0; q < 4; q++) {
                const __half* rp = (q & 1) ? r1 : r0;
                int cofs = c0 + ((q >> 1) ? 8 : 0);
                float2 f = __half22float2(*(const __half2*)(rp + cofs));
                __half2 v = __floats2half2_rn(f.x * SC, f.y * SC);
                qf[kf][q] = *(unsigned*)&v;
            }
        }
    }

    float of[8][4];
#pragma unroll
    for (int nf = 0; nf < 8; nf++)
#pragma unroll
        for (int q = 0; q < 4; q++) of[nf][q] = 0.f;
    float m0 = -1e30f, m1 = -1e30f, l0 = 0.f, l1 = 0.f;

    for (int t = 0; t < SEQ / 64; t++) {
        if (t + 1 < SEQ / 64) { load_kv((t + 1) * 64, (t + 1) & 1); cp_wait1(); }
        else cp_wait0();
        __syncthreads();

        const char* K = ksm + (t & 1) * KSW_BYTES;
        const unsigned* V = vtsm + (t & 1) * (VT_BYTES / 4);

        // ---- S = Q K^T (log2 domain) ----
        float s[8][4];
#pragma unroll
        for (int nf = 0; nf < 8; nf++) {
#pragma unroll
            for (int q = 0; q < 4; q++) s[nf][q] = 0.f;
            int r = nf * 8 + gg;
            unsigned sw = (unsigned)(r & 7) << 4;
#pragma unroll
            for (int kf = 0; kf < 4; kf++) {
                unsigned off0 = r * 128 + (kf * 16 + 2 * cc) * 2;
                unsigned bfr[2];
                bfr[0] = *(const unsigned*)(K + (off0 ^ sw));
                bfr[1] = *(const unsigned*)(K + ((off0 + 16) ^ sw));
                mma_fp16(s[nf], qf[kf], bfr);
            }
        }

        // ---- online softmax (log2 domain; P via dual fp16 ex2) ----
        float rmax0 = -1e30f, rmax1 = -1e30f;
#pragma unroll
        for (int nf = 0; nf < 8; nf++) {
            rmax0 = fmaxf(rmax0, fmaxf(s[nf][0], s[nf][1]));
            rmax1 = fmaxf(rmax1, fmaxf(s[nf][2], s[nf][3]));
        }
        rmax0 = fmaxf(rmax0, __shfl_xor_sync(0xffffffffu, rmax0, 1));
        rmax0 = fmaxf(rmax0, __shfl_xor_sync(0xffffffffu, rmax0, 2));
        rmax1 = fmaxf(rmax1, __shfl_xor_sync(0xffffffffu, rmax1, 1));
        rmax1 = fmaxf(rmax1, __shfl_xor_sync(0xffffffffu, rmax1, 2));

        float mn0 = fmaxf(m0, rmax0);
        float mn1 = fmaxf(m1, rmax1);
        float f0 = exp2f(m0 - mn0);
        float f1 = exp2f(m1 - mn1);
        m0 = mn0; m1 = mn1;

        float rs0 = 0.f, rs1 = 0.f;
#pragma unroll
        for (int nf = 0; nf < 8; nf++) {
            __half2 hd0 = __floats2half2_rn(s[nf][0] - mn0, s[nf][1] - mn0);
            __half2 hd1 = __floats2half2_rn(s[nf][2] - mn1, s[nf][3] - mn1);
            unsigned hp0 = ex2_f16x2(*(unsigned*)&hd0);
            unsigned hp1 = ex2_f16x2(*(unsigned*)&hd1);
            float2 pf0 = __half22float2(*(__half2*)&hp0);
            float2 pf1 = __half22float2(*(__half2*)&hp1);
            rs0 += pf0.x + pf0.y;
            rs1 += pf1.x + pf1.y;
            p2sm[(wm + gg) * P2_STRIDE + nf * 4 + cc] = hp0;
            p2sm[(wm + gg + 8) * P2_STRIDE + nf * 4 + cc] = hp1;
        }
        rs0 += __shfl_xor_sync(0xffffffffu, rs0, 1);
        rs0 += __shfl_xor_sync(0xffffffffu, rs0, 2);
        rs1 += __shfl_xor_sync(0xffffffffu, rs1, 1);
        rs1 += __shfl_xor_sync(0xffffffffu, rs1, 2);
        l0 = l0 * f0 + rs0;
        l1 = l1 * f1 + rs1;

#pragma unroll
        for (int nf = 0; nf < 8; nf++) {
            of[nf][0] *= f0; of[nf][1] *= f0;
            of[nf][2] *= f1; of[nf][3] *= f1;
        }
        __syncwarp();

        // ---- O += P V ----
#pragma unroll
        for (int kf = 0; kf < 4; kf++) {
            unsigned a[4];
            a[0] = p2sm[(wm + gg) * P2_STRIDE + kf * 8 + cc];
            a[1] = p2sm[(wm + gg + 8) * P2_STRIDE + kf * 8 + cc];
            a[2] = p2sm[(wm + gg) * P2_STRIDE + kf * 8 + cc + 4];
            a[3] = p2sm[(wm + gg + 8) * P2_STRIDE + kf * 8 + cc + 4];
#pragma unroll
            for (int nf = 0; nf < 8; nf++) {
                unsigned bfr[2];
                bfr[0] = V[(nf * 8 + gg) * VT_STRIDE + kf * 8 + cc];
                bfr[1] = V[(nf * 8 + gg) * VT_STRIDE + kf * 8 + cc + 4];
                mma_fp16(of[nf], a, bfr);
            }
        }
        __syncthreads();
    }

    // ---- epilogue ----
    float inv0 = 1.0f / l0;
    float inv1 = 1.0f / l1;
    __half* op = out + tokbase * DIM + h * DH;
#pragma unroll
    for (int nf = 0; nf < 8; nf++) {
        int c0 = nf * 8 + 2 * cc;
        __half2 w0 = __floats2half2_rn(of[nf][0] * inv0, of[nf][1] * inv0);
        __half2 w1 = __floats2half2_rn(of[nf][2] * inv1, of[nf][3] * inv1);
        *(__half2*)(op + (size_t)(wm + gg) * DIM + c0)     = w0;
        *(__half2*)(op + (size_t)(wm + gg + 8) * DIM + c0) = w1;
    }
}

// =====================================================================
// launch
// =====================================================================
extern "C" void kernel_launch(void* const* d_in, const int* in_sizes, int n_in,
                              void* d_out, int out_size)
{
    const float* x      = (const float*)d_in[0];
    const float* w_qkv  = (const float*)d_in[1];
    const float* w_out  = (const float*)d_in[2];
    const float* b_out  = (const float*)d_in[3];
    const float* w1     = (const float*)d_in[4];
    const float* b1     = (const float*)d_in[5];
    const float* w2     = (const float*)d_in[6];
    const float* b2     = (const float*)d_in[7];
    const float* gamma1 = (const float*)d_in[8];
    const float* beta1  = (const float*)d_in[9];
    const float* gamma2 = (const float*)d_in[10];
    const float* beta2  = (const float*)d_in[11];
    float* out = (float*)d_out;

    __half *xn, *qkv, *att, *h, *ff;
    float *x1;
    unsigned *wqkv, *wout, *w1p, *w2p;
    cudaGetSymbolAddress((void**)&xn,   g_xn);
    cudaGetSymbolAddress((void**)&qkv,  g_qkv);
    cudaGetSymbolAddress((void**)&att,  g_att);
    cudaGetSymbolAddress((void**)&x1,   g_x1);
    cudaGetSymbolAddress((void**)&h,    g_h);
    cudaGetSymbolAddress((void**)&ff,   g_ff);
    cudaGetSymbolAddress((void**)&wqkv, g_wqkv);
    cudaGetSymbolAddress((void**)&wout, g_wout);
    cudaGetSymbolAddress((void**)&w1p,  g_w1);
    cudaGetSymbolAddress((void**)&w2p,  g_w2);

    static bool attr_done = false;
    if (!attr_done) {
        cudaFuncSetAttribute(gemm_fp16_kernel<__half, false, false, false>,
                             cudaFuncAttributeMaxDynamicSharedMemorySize, GEMM_SMEM_BYTES);
        cudaFuncSetAttribute(gemm_fp16_kernel<float, true, false, true>,
                             cudaFuncAttributeMaxDynamicSharedMemorySize, GEMM_SMEM_BYTES);
        cudaFuncSetAttribute(gemm_fp16_kernel<__half, true, true, false>,
                             cudaFuncAttributeMaxDynamicSharedMemorySize, GEMM_SMEM_BYTES);
        cudaFuncSetAttribute(attn_fp16_kernel,
                             cudaFuncAttributeMaxDynamicSharedMemorySize, ATTF_SMEM);
        attr_done = true;
    }

    // 0) pack weights to fp16 k-paired layout
    pack_w_kernel<<<dim3(3 * DIM / 256, DIM / 2), 256>>>(w_qkv, wqkv, DIM, 3 * DIM);
    pack_w_kernel<<<dim3(DIM / 256, DIM / 2), 256>>>(w_out, wout, DIM, DIM);
    pack_w_kernel<<<dim3(HID / 256, DIM / 2), 256>>>(w1, w1p, DIM, HID);
    pack_w_kernel<<<dim3(DIM / 256, HID / 2), 256>>>(w2, w2p, HID, DIM);

    // 1) xn = fp16(LN1(x))
    ln_kernel<<<TOK, 256>>>(x, gamma1, beta1, xn);

    // 2) qkv = fp16(xn @ w_qkv)
    gemm_fp16_kernel<__half, false, false, false>
        <<<dim3(3 * DIM / 128, TOK / 128), 128, GEMM_SMEM_BYTES>>>(
        xn, wqkv, nullptr, nullptr, qkv, TOK, 3 * DIM, DIM);

    // 3) att = fp16(attention(qkv))
    attn_fp16_kernel<<<dim3(SEQ / 128, BATCH * HEADS), 256, ATTF_SMEM>>>(qkv, att);

    // 4) x1 = x + att @ w_out + b_out    (fp32)
    gemm_fp16_kernel<float, true, false, true>
        <<<dim3(DIM / 128, TOK / 128), 128, GEMM_SMEM_BYTES>>>(
        att, wout, b_out, x, x1, TOK, DIM, DIM);

    // 5) h = fp16(LN2(x1))
    ln_kernel<<<TOK, 256>>>(x1, gamma2, beta2, h);

    // 6) ff = fp16(relu(h @ w1 + b1))
    gemm_fp16_kernel<__half, true, true, false>
        <<<dim3(HID / 128, TOK / 128), 128, GEMM_SMEM_BYTES>>>(
        h, w1p, b1, nullptr, ff, TOK, HID, DIM);

    // 7) out = x1 + ff @ w2 + b2   (fp32)
    gemm_fp16_kernel<float, true, false, true>
        <<<dim3(DIM / 128, TOK / 128), 128, GEMM_SMEM_BYTES>>>(
        ff, w2p, b2, x1, out, TOK, DIM, HID);
}

// round 10
// speedup vs baseline: 13.3167x; 1.1179x over previous
#include <cuda_runtime.h>
#include <cuda_fp16.h>
#include <math.h>
#include <stddef.h>
#include <stdint.h>

// ---------------- problem constants ----------------
#define BATCH   4
#define SEQ     2048
#define DIM     1024
#define HEADS   16
#define DH      64
#define HID     4096
#define TOK     (BATCH * SEQ)          // 8192
#define EPS     1e-5f
#define ATT_SCALE 0.03125f             // DIM^-0.5 = 1/32
#define LOG2E   1.44269504088896f

// ---------------- scratch (no cudaMalloc allowed) ----------------
__device__ __half g_xn [TOK * DIM];
__device__ __half g_qkv[TOK * 3 * DIM];
__device__ __half g_att[TOK * DIM];
__device__ float  g_x1 [TOK * DIM];
__device__ __half g_h  [TOK * DIM];
__device__ __half g_ff [TOK * HID];
// packed fp16 weights: [K/2][N] of half2 (k-pairs)
__device__ unsigned g_wqkv[(DIM / 2) * 3 * DIM];
__device__ unsigned g_wout[(DIM / 2) * DIM];
__device__ unsigned g_w1  [(DIM / 2) * HID];
__device__ unsigned g_w2  [(HID / 2) * DIM];

// ---------------- helpers ----------------
__device__ __forceinline__ void cp16(unsigned dst, const void* src) {
    asm volatile("cp.async.cg.shared.global [%0], [%1], 16;" :: "r"(dst), "l"(src));
}
__device__ __forceinline__ void cp_commit() {
    asm volatile("cp.async.commit_group;" ::: "memory");
}
__device__ __forceinline__ void cp_wait0() {
    asm volatile("cp.async.wait_group 0;" ::: "memory");
}

// fp16 mma, fp32 accumulate: D(16x8) += A(16x16) B(16x8)
__device__ __forceinline__ void mma_fp16(
    float* c, const unsigned* a, unsigned b0, unsigned b1)
{
    asm volatile(
        "mma.sync.aligned.m16n8k16.row.col.f32.f16.f16.f32 "
        "{%0,%1,%2,%3}, {%4,%5,%6,%7}, {%8,%9}, {%0,%1,%2,%3};"
        : "+f"(c[0]), "+f"(c[1]), "+f"(c[2]), "+f"(c[3])
        : "r"(a[0]), "r"(a[1]), "r"(a[2]), "r"(a[3]), "r"(b0), "r"(b1));
}

__device__ __forceinline__ void ldsm_x4(
    unsigned& d0, unsigned& d1, unsigned& d2, unsigned& d3, unsigned addr)
{
    asm volatile("ldmatrix.sync.aligned.m8n8.x4.shared.b16 {%0,%1,%2,%3}, [%4];"
                 : "=r"(d0), "=r"(d1), "=r"(d2), "=r"(d3) : "r"(addr));
}
__device__ __forceinline__ void ldsm_x4_t(
    unsigned& d0, unsigned& d1, unsigned& d2, unsigned& d3, unsigned addr)
{
    asm volatile("ldmatrix.sync.aligned.m8n8.x4.trans.shared.b16 {%0,%1,%2,%3}, [%4];"
                 : "=r"(d0), "=r"(d1), "=r"(d2), "=r"(d3) : "r"(addr));
}

// dual fp16 exp2
__device__ __forceinline__ unsigned ex2_f16x2(unsigned in) {
    unsigned out;
    asm("ex2.approx.f16x2 %0, %1;" : "=r"(out) : "r"(in));
    return out;
}

// =====================================================================
// weight pack: out[k2][n] = half2(w[2k2][n], w[2k2+1][n])
// =====================================================================
__global__ void __launch_bounds__(256) pack_w_kernel(
    const float* __restrict__ w, unsigned* __restrict__ out, int K, int N)
{
    int n = blockIdx.x * 256 + threadIdx.x;
    int k2 = blockIdx.y;
    float lo = w[(size_t)(2 * k2) * N + n];
    float hi = w[(size_t)(2 * k2 + 1) * N + n];
    __half2 h = __floats2half2_rn(lo, hi);
    out[(size_t)k2 * N + n] = *(unsigned*)&h;
}

// =====================================================================
// LayerNorm (torch semantics), fp16 output.
// =====================================================================
__global__ void __launch_bounds__(256) ln_kernel(
    const float* __restrict__ x, const float* __restrict__ gamma,
    const float* __restrict__ beta, __half* __restrict__ y)
{
    int row = blockIdx.x;
    int t = threadIdx.x;
    const float* xr = x + (size_t)row * DIM;
    float4 v = *(const float4*)(xr + t * 4);

    __shared__ float red[8];

    float s = v.x + v.y + v.z + v.w;
#pragma unroll
    for (int o = 16; o > 0; o >>= 1) s += __shfl_xor_sync(0xffffffffu, s, o);
    if ((t & 31) == 0) red[t >> 5] = s;
    __syncthreads();
    float tot = 0.f;
#pragma unroll
    for (int i = 0; i < 8; i++) tot += red[i];
    float mean = tot * (1.0f / DIM);

    float dx = v.x - mean, dy = v.y - mean, dz = v.z - mean, dw = v.w - mean;
    float ss = dx * dx + dy * dy + dz * dz + dw * dw;
#pragma unroll
    for (int o = 16; o > 0; o >>= 1) ss += __shfl_xor_sync(0xffffffffu, ss, o);
    __syncthreads();
    if ((t & 31) == 0) red[t >> 5] = ss;
    __syncthreads();
    float tss = 0.f;
#pragma unroll
    for (int i = 0; i < 8; i++) tss += red[i];

    float inv = 1.0f / (sqrtf(tss * (1.0f / (DIM - 1))) + EPS);

    float4 gv = *(const float4*)(gamma + t * 4);
    float4 bv = *(const float4*)(beta + t * 4);
    __half2 h01 = __floats2half2_rn(gv.x * dx * inv + bv.x, gv.y * dy * inv + bv.y);
    __half2 h23 = __floats2half2_rn(gv.z * dz * inv + bv.z, gv.w * dw * inv + bv.w);
    __half2* yp = (__half2*)(y + (size_t)row * DIM + t * 4);
    yp[0] = h01;
    yp[1] = h23;
}

// =====================================================================
// fp16 tensor-core GEMM. BM=BN=128, BK=64 halves, 128 threads = 4 warps.
// A-frags via ldmatrix.x4; single __syncthreads per K-tile.
// =====================================================================
#define AH_STRIDE 72
#define A_BUF_BYTES (128 * AH_STRIDE * 2)     // 18432
#define BW_STRIDE 136
#define B_BUF_BYTES (32 * BW_STRIDE * 4)      // 17408
#define GEMM_SMEM_BYTES (2 * A_BUF_BYTES + 2 * B_BUF_BYTES)   // 71680

template <typename OutT, bool BIAS, bool RELU, bool RES>
__global__ void __launch_bounds__(128, 2) gemm_fp16_kernel(
    const __half* __restrict__ A, const unsigned* __restrict__ Bp,
    const float* __restrict__ bias, const float* __restrict__ res,
    OutT* __restrict__ C, int M, int N, int K)
{
    extern __shared__ char smraw[];
    unsigned sbase = (unsigned)__cvta_generic_to_shared(smraw);
    const unsigned* Bs_all = (const unsigned*)(smraw + 2 * A_BUF_BYTES);

    int tid = threadIdx.x;
    int warp = tid >> 5;
    int lane = tid & 31;
    int bm = blockIdx.y * 128;
    int bn = blockIdx.x * 128;
    int wm = (warp & 1) * 64;
    int wn = (warp >> 1) * 64;
    int gg = lane >> 2;
    int cc = lane & 3;

    float acc[4][8][4];
#pragma unroll
    for (int f = 0; f < 4; f++)
#pragma unroll
        for (int nf = 0; nf < 8; nf++)
#pragma unroll
            for (int q = 0; q < 4; q++) acc[f][nf][q] = 0.f;

    auto load_tiles = [&](int t, int s) {
        int k0 = t * 64;
        unsigned abase = sbase + s * A_BUF_BYTES;
        unsigned bbase = sbase + 2 * A_BUF_BYTES + s * B_BUF_BYTES;
#pragma unroll
        for (int j = 0; j < 8; j++) {
            int idx = tid + j * 128;
            int r = idx >> 3, c = idx & 7;
            cp16(abase + r * (AH_STRIDE * 2) + c * 16,
                 A + (size_t)(bm + r) * K + k0 + c * 8);
        }
#pragma unroll
        for (int j = 0; j < 8; j++) {
            int idx = tid + j * 128;
            int r = idx >> 5, c4 = idx & 31;
            cp16(bbase + r * (BW_STRIDE * 4) + c4 * 16,
                 Bp + (size_t)(t * 32 + r) * N + bn + c4 * 4);
        }
        cp_commit();
    };

    int nT = K >> 6;
    load_tiles(0, 0);

    // per-lane ldmatrix row/col components (constant across tiles)
    int lrow = lane & 15;
    int lkof = (lane & 16) ? 8 : 0;

    for (int t = 0; t < nT; t++) {
        cp_wait0();
        __syncthreads();
        if (t + 1 < nT) load_tiles(t + 1, (t + 1) & 1);

        unsigned abase = sbase + (t & 1) * A_BUF_BYTES;
        const unsigned* bs = (const unsigned*)((const char*)Bs_all + (t & 1) * B_BUF_BYTES);

#pragma unroll
        for (int ks = 0; ks < 4; ks++) {
            int kb = ks * 16;
            unsigned a[4][4], b[8][2];
#pragma unroll
            for (int f = 0; f < 4; f++) {
                unsigned addr = abase +
                    ((unsigned)(wm + f * 16 + lrow) * AH_STRIDE + (unsigned)(kb + lkof)) * 2;
                ldsm_x4(a[f][0], a[f][1], a[f][2], a[f][3], addr);
            }
#pragma unroll
            for (int nf = 0; nf < 8; nf++) {
                int col = wn + nf * 8 + gg;
                b[nf][0] = bs[(kb / 2 + cc) * BW_STRIDE + col];
                b[nf][1] = bs[(kb / 2 + cc + 4) * BW_STRIDE + col];
            }
#pragma unroll
            for (int f = 0; f < 4; f++)
#pragma unroll
                for (int nf = 0; nf < 8; nf++)
                    mma_fp16(acc[f][nf], a[f], b[nf][0], b[nf][1]);
        }
    }

#pragma unroll
    for (int f = 0; f < 4; f++) {
#pragma unroll
        for (int nf = 0; nf < 8; nf++) {
            int col = bn + wn + nf * 8 + 2 * cc;
#pragma unroll
            for (int half_i = 0; half_i < 2; half_i++) {
                int row = bm + wm + f * 16 + gg + half_i * 8;
                float v0 = acc[f][nf][half_i * 2 + 0];
                float v1 = acc[f][nf][half_i * 2 + 1];
                if (BIAS) { v0 += bias[col]; v1 += bias[col + 1]; }
                if (RES) {
                    const float* rp = res + (size_t)row * N + col;
                    v0 += rp[0]; v1 += rp[1];
                }
                if (RELU) { v0 = fmaxf(v0, 0.f); v1 = fmaxf(v1, 0.f); }
                if (sizeof(OutT) == 2) {
                    __half2 hv = __floats2half2_rn(v0, v1);
                    *(__half2*)((__half*)C + (size_t)row * N + col) = hv;
                } else {
                    float2 w; w.x = v0; w.y = v1;
                    *(float2*)((float*)C + (size_t)row * N + col) = w;
                }
            }
        }
    }
}

// =====================================================================
// fp16 flash attention: all operands via ldmatrix, all loads cp.async,
// log2-domain softmax with ex2.approx.f16x2, 1 sync per tile.
// grid (SEQ/128, BATCH*HEADS), 256 threads = 8 warps, 16 q-rows/warp.
// smem: K 2x8KB | V 2x8KB | P 128x36 words = 51200 B -> 2 CTA/SM.
// =====================================================================
#define KSW_BYTES 8192
#define P2_STRIDE 36
#define P2_BYTES  (128 * P2_STRIDE * 4)       // 18432
#define ATTF_SMEM (4 * KSW_BYTES + P2_BYTES)  // 51200

__global__ void __launch_bounds__(256) attn_fp16_kernel(
    const __half* __restrict__ qkv, __half* __restrict__ out)
{
    extern __shared__ char sm[];
    unsigned sbase = (unsigned)__cvta_generic_to_shared(sm);
    unsigned* p2sm = (unsigned*)(sm + 4 * KSW_BYTES);
    unsigned p2base = sbase + 4 * KSW_BYTES;

    int tid = threadIdx.x;
    int warp = tid >> 5;
    int lane = tid & 31;
    int gg = lane >> 2;
    int cc = lane & 3;
    int wm = warp * 16;

    int bh = blockIdx.y;
    int b = bh >> 4;
    int h = bh & 15;
    size_t tokbase = (size_t)b * SEQ + blockIdx.x * 128;
    const __half* qb = qkv + tokbase * (3 * DIM) + h * DH;

    // K and V tiles: 64 rows x 128B each, XOR-swizzled, pure cp.async
    auto load_kv = [&](int kt, int s) {
        const __half* kp = qkv + ((size_t)b * SEQ + kt) * (3 * DIM) + DIM + h * DH;
        const __half* vp = kp + DIM;
        unsigned kdst = sbase + s * KSW_BYTES;
        unsigned vdst = sbase + (2 + s) * KSW_BYTES;
#pragma unroll
        for (int j = 0; j < 2; j++) {
            int idx = tid + j * 256;
            int r = idx >> 3, c = idx & 7;
            unsigned off = (unsigned)(r * 128 + c * 16);
            unsigned sw = off ^ ((unsigned)(r & 7) << 4);
            cp16(kdst + sw, kp + (size_t)r * (3 * DIM) + c * 8);
            cp16(vdst + sw, vp + (size_t)r * (3 * DIM) + c * 8);
        }
        cp_commit();
    };

    load_kv(0, 0);

    // ---- preload Q fragments scaled by ATT_SCALE*log2e ----
    unsigned qf[4][4];
    {
        const float SC = ATT_SCALE * LOG2E;
        const __half* r0 = qb + (size_t)(wm + gg) * (3 * DIM);
        const __half* r1 = qb + (size_t)(wm + gg + 8) * (3 * DIM);
#pragma unroll
        for (int kf = 0; kf < 4; kf++) {
            int c0 = kf * 16 + 2 * cc;
#pragma unroll
            for (int q = 0; q < 4; q++) {
                const __half* rp = (q & 1) ? r1 : r0;
                int cofs = c0 + ((q >> 1) ? 8 : 0);
                float2 f = __half22float2(*(const __half2*)(rp + cofs));
                __half2 v = __floats2half2_rn(f.x * SC, f.y * SC);
                qf[kf][q] = *(unsigned*)&v;
            }
        }
    }

    float of[8][4];
#pragma unroll
    for (int nf = 0; nf < 8; nf++)
#pragma unroll
        for (int q = 0; q < 4; q++) of[nf][q] = 0.f;
    float m0 = -1e30f, m1 = -1e30f, l0 = 0.f, l1 = 0.f;

    int l15 = lane & 15;

    for (int t = 0; t < SEQ / 64; t++) {
        cp_wait0();
        __syncthreads();
        if (t + 1 < SEQ / 64) load_kv((t + 1) * 64, (t + 1) & 1);

        unsigned kb_s = sbase + (t & 1) * KSW_BYTES;
        unsigned vb_s = sbase + (2 + (t & 1)) * KSW_BYTES;

        // ---- S = Q K^T : b-frags via ldmatrix.x4 (non-trans) ----
        float s[8][4];
#pragma unroll
        for (int nf = 0; nf < 8; nf++)
#pragma unroll
            for (int q = 0; q < 4; q++) s[nf][q] = 0.f;

#pragma unroll
        for (int kf = 0; kf < 4; kf++) {
#pragma unroll
            for (int nfp = 0; nfp < 4; nfp++) {
                unsigned row = (unsigned)(nfp * 16 + (lane & 7) + ((lane & 16) ? 8 : 0));
                unsigned off = row * 128 + (unsigned)(kf * 32 + ((lane & 8) ? 16 : 0));
                unsigned addr = kb_s + (off ^ ((row & 7) << 4));
                unsigned b0, b1, b2, b3;
                ldsm_x4(b0, b1, b2, b3, addr);
                mma_fp16(s[2 * nfp], qf[kf], b0, b1);
                mma_fp16(s[2 * nfp + 1], qf[kf], b2, b3);
            }
        }

        // ---- online softmax (log2 domain) ----
        float rmax0 = -1e30f, rmax1 = -1e30f;
#pragma unroll
        for (int nf = 0; nf < 8; nf++) {
            rmax0 = fmaxf(rmax0, fmaxf(s[nf][0], s[nf][1]));
            rmax1 = fmaxf(rmax1, fmaxf(s[nf][2], s[nf][3]));
        }
        rmax0 = fmaxf(rmax0, __shfl_xor_sync(0xffffffffu, rmax0, 1));
        rmax0 = fmaxf(rmax0, __shfl_xor_sync(0xffffffffu, rmax0, 2));
        rmax1 = fmaxf(rmax1, __shfl_xor_sync(0xffffffffu, rmax1, 1));
        rmax1 = fmaxf(rmax1, __shfl_xor_sync(0xffffffffu, rmax1, 2));

        float mn0 = fmaxf(m0, rmax0);
        float mn1 = fmaxf(m1, rmax1);
        float f0 = exp2f(m0 - mn0);
        float f1 = exp2f(m1 - mn1);
        m0 = mn0; m1 = mn1;

        float rs0 = 0.f, rs1 = 0.f;
#pragma unroll
        for (int nf = 0; nf < 8; nf++) {
            __half2 hd0 = __floats2half2_rn(s[nf][0] - mn0, s[nf][1] - mn0);
            __half2 hd1 = __floats2half2_rn(s[nf][2] - mn1, s[nf][3] - mn1);
            unsigned hp0 = ex2_f16x2(*(unsigned*)&hd0);
            unsigned hp1 = ex2_f16x2(*(unsigned*)&hd1);
            float2 pf0 = __half22float2(*(__half2*)&hp0);
            float2 pf1 = __half22float2(*(__half2*)&hp1);
            rs0 += pf0.x + pf0.y;
            rs1 += pf1.x + pf1.y;
            p2sm[(wm + gg) * P2_STRIDE + nf * 4 + cc] = hp0;
            p2sm[(wm + gg + 8) * P2_STRIDE + nf * 4 + cc] = hp1;
        }
        rs0 += __shfl_xor_sync(0xffffffffu, rs0, 1);
        rs0 += __shfl_xor_sync(0xffffffffu, rs0, 2);
        rs1 += __shfl_xor_sync(0xffffffffu, rs1, 1);
        rs1 += __shfl_xor_sync(0xffffffffu, rs1, 2);
        l0 = l0 * f0 + rs0;
        l1 = l1 * f1 + rs1;

#pragma unroll
        for (int nf = 0; nf < 8; nf++) {
            of[nf][0] *= f0; of[nf][1] *= f0;
            of[nf][2] *= f1; of[nf][3] *= f1;
        }
        __syncwarp();

        // ---- O += P V : a-frags (P) ldmatrix.x4, b-frags (V) ldmatrix.x4.trans
#pragma unroll
        for (int kf = 0; kf < 4; kf++) {
            unsigned a[4];
            unsigned pa = p2base + (unsigned)(wm + l15) * (P2_STRIDE * 4)
                        + (unsigned)(kf * 32 + ((lane & 16) ? 16 : 0));
            ldsm_x4(a[0], a[1], a[2], a[3], pa);
#pragma unroll
            for (int nfp = 0; nfp < 4; nfp++) {
                unsigned row = (unsigned)(kf * 16 + l15);
                unsigned off = row * 128 + (unsigned)(nfp * 32 + ((lane & 16) ? 16 : 0));
                unsigned addr = vb_s + (off ^ ((row & 7) << 4));
                unsigned b0, b1, b2, b3;
                ldsm_x4_t(b0, b1, b2, b3, addr);
                mma_fp16(of[2 * nfp], a, b0, b1);
                mma_fp16(of[2 * nfp + 1], a, b2, b3);
            }
        }
    }

    // ---- epilogue ----
    float inv0 = 1.0f / l0;
    float inv1 = 1.0f / l1;
    __half* op = out + tokbase * DIM + h * DH;
#pragma unroll
    for (int nf = 0; nf < 8; nf++) {
        int c0 = nf * 8 + 2 * cc;
        __half2 w0 = __floats2half2_rn(of[nf][0] * inv0, of[nf][1] * inv0);
        __half2 w1 = __floats2half2_rn(of[nf][2] * inv1, of[nf][3] * inv1);
        *(__half2*)(op + (size_t)(wm + gg) * DIM + c0)     = w0;
        *(__half2*)(op + (size_t)(wm + gg + 8) * DIM + c0) = w1;
    }
}

// =====================================================================
// launch
// =====================================================================
extern "C" void kernel_launch(void* const* d_in, const int* in_sizes, int n_in,
                              void* d_out, int out_size)
{
    const float* x      = (const float*)d_in[0];
    const float* w_qkv  = (const float*)d_in[1];
    const float* w_out  = (const float*)d_in[2];
    const float* b_out  = (const float*)d_in[3];
    const float* w1     = (const float*)d_in[4];
    const float* b1     = (const float*)d_in[5];
    const float* w2     = (const float*)d_in[6];
    const float* b2     = (const float*)d_in[7];
    const float* gamma1 = (const float*)d_in[8];
    const float* beta1  = (const float*)d_in[9];
    const float* gamma2 = (const float*)d_in[10];
    const float* beta2  = (const float*)d_in[11];
    float* out = (float*)d_out;

    __half *xn, *qkv, *att, *h, *ff;
    float *x1;
    unsigned *wqkv, *wout, *w1p, *w2p;
    cudaGetSymbolAddress((void**)&xn,   g_xn);
    cudaGetSymbolAddress((void**)&qkv,  g_qkv);
    cudaGetSymbolAddress((void**)&att,  g_att);
    cudaGetSymbolAddress((void**)&x1,   g_x1);
    cudaGetSymbolAddress((void**)&h,    g_h);
    cudaGetSymbolAddress((void**)&ff,   g_ff);
    cudaGetSymbolAddress((void**)&wqkv, g_wqkv);
    cudaGetSymbolAddress((void**)&wout, g_wout);
    cudaGetSymbolAddress((void**)&w1p,  g_w1);
    cudaGetSymbolAddress((void**)&w2p,  g_w2);

    static bool attr_done = false;
    if (!attr_done) {
        cudaFuncSetAttribute(gemm_fp16_kernel<__half, false, false, false>,
                             cudaFuncAttributeMaxDynamicSharedMemorySize, GEMM_SMEM_BYTES);
        cudaFuncSetAttribute(gemm_fp16_kernel<float, true, false, true>,
                             cudaFuncAttributeMaxDynamicSharedMemorySize, GEMM_SMEM_BYTES);
        cudaFuncSetAttribute(gemm_fp16_kernel<__half, true, true, false>,
                             cudaFuncAttributeMaxDynamicSharedMemorySize, GEMM_SMEM_BYTES);
        cudaFuncSetAttribute(attn_fp16_kernel,
                             cudaFuncAttributeMaxDynamicSharedMemorySize, ATTF_SMEM);
        attr_done = true;
    }

    // 0) pack weights to fp16 k-paired layout
    pack_w_kernel<<<dim3(3 * DIM / 256, DIM / 2), 256>>>(w_qkv, wqkv, DIM, 3 * DIM);
    pack_w_kernel<<<dim3(DIM / 256, DIM / 2), 256>>>(w_out, wout, DIM, DIM);
    pack_w_kernel<<<dim3(HID / 256, DIM / 2), 256>>>(w1, w1p, DIM, HID);
    pack_w_kernel<<<dim3(DIM / 256, HID / 2), 256>>>(w2, w2p, HID, DIM);

    // 1) xn = fp16(LN1(x))
    ln_kernel<<<TOK, 256>>>(x, gamma1, beta1, xn);

    // 2) qkv = fp16(xn @ w_qkv)
    gemm_fp16_kernel<__half, false, false, false>
        <<<dim3(3 * DIM / 128, TOK / 128), 128, GEMM_SMEM_BYTES>>>(
        xn, wqkv, nullptr, nullptr, qkv, TOK, 3 * DIM, DIM);

    // 3) att = fp16(attention(qkv))
    attn_fp16_kernel<<<dim3(SEQ / 128, BATCH * HEADS), 256, ATTF_SMEM>>>(qkv, att);

    // 4) x1 = x + att @ w_out + b_out    (fp32)
    gemm_fp16_kernel<float, true, false, true>
        <<<dim3(DIM / 128, TOK / 128), 128, GEMM_SMEM_BYTES>>>(
        att, wout, b_out, x, x1, TOK, DIM, DIM);

    // 5) h = fp16(LN2(x1))
    ln_kernel<<<TOK, 256>>>(x1, gamma2, beta2, h);

    // 6) ff = fp16(relu(h @ w1 + b1))
    gemm_fp16_kernel<__half, true, true, false>
        <<<dim3(HID / 128, TOK / 128), 128, GEMM_SMEM_BYTES>>>(
        h, w1p, b1, nullptr, ff, TOK, HID, DIM);

    // 7) out = x1 + ff @ w2 + b2   (fp32)
    gemm_fp16_kernel<float, true, false, true>
        <<<dim3(DIM / 128, TOK / 128), 128, GEMM_SMEM_BYTES>>>(
        ff, w2p, b2, x1, out, TOK, DIM, HID);
}